// round 6
// baseline (speedup 1.0000x reference)
#include <cuda_runtime.h>
#include <math.h>
#include <stdint.h>

// Problem constants
#define DIN   256
#define HCc   256
#define NEG   0.2f
#define MAXN  50000
#define MAXE  1000000

// ---------------- scratch (static device globals) --------------------------
__device__ float g_XL1[(long long)MAXN * HCc];
__device__ float g_XR1[(long long)MAXN * HCc];
__device__ float g_SKIP[(long long)MAXN * HCc];
__device__ float g_XL2[MAXN * 2];
__device__ float g_XR2[MAXN * 2];
__device__ int   g_deg[MAXN];
__device__ int   g_rowptr[MAXN + 1];
__device__ int   g_cur[MAXN];
__device__ int   g_esrc[MAXE];
__device__ int   g_bsum[64];
__device__ int   g_boff[64];
__device__ int   g_is64;

// ---------------- packed f32x2 helpers --------------------------------------
__device__ __forceinline__ unsigned long long f32x2_fma(unsigned long long a,
                                                        unsigned long long b,
                                                        unsigned long long c) {
    unsigned long long d;
    asm("fma.rn.f32x2 %0, %1, %2, %3;" : "=l"(d) : "l"(a), "l"(b), "l"(c));
    return d;
}
__device__ __forceinline__ unsigned long long f32x2_add(unsigned long long a,
                                                        unsigned long long b) {
    unsigned long long d;
    asm("add.rn.f32x2 %0, %1, %2;" : "=l"(d) : "l"(a), "l"(b));
    return d;
}

// ---------------- dtype detection for edge_index (int32 vs int64) ---------
__global__ void detect_idx_kernel(const unsigned int* __restrict__ w) {
    int ok = 1;
    #pragma unroll
    for (int i = 0; i < 32; i++) {
        if (w[2 * i + 1] != 0u) { ok = 0; break; }
    }
    g_is64 = ok;
}
__device__ __forceinline__ int ld_idx(const void* ei, long long pos, int is64) {
    if (is64) return (int)(((const long long*)ei)[pos]);
    return ((const int*)ei)[pos];
}

// ---------------- CSR build -------------------------------------------------
__global__ void zero_deg_kernel(int N) {
    int i = blockIdx.x * blockDim.x + threadIdx.x;
    if (i < N) g_deg[i] = 0;
}
__global__ void hist_kernel(const void* __restrict__ ei, long long E) {
    long long e = (long long)blockIdx.x * blockDim.x + threadIdx.x;
    if (e >= E) return;
    int dst = ld_idx(ei, E + e, g_is64);
    atomicAdd(&g_deg[dst], 1);
}
__global__ __launch_bounds__(1024) void scanA_kernel(int N) {
    __shared__ int wsum[32];
    const int lane = threadIdx.x & 31, warp = threadIdx.x >> 5;
    int i = blockIdx.x * 1024 + threadIdx.x;
    int v = (i < N) ? g_deg[i] : 0;
    int x = v;
    #pragma unroll
    for (int o = 1; o < 32; o <<= 1) {
        int y = __shfl_up_sync(0xffffffffu, x, o);
        if (lane >= o) x += y;
    }
    if (lane == 31) wsum[warp] = x;
    __syncthreads();
    if (warp == 0) {
        int w = wsum[lane];
        #pragma unroll
        for (int o = 1; o < 32; o <<= 1) {
            int y = __shfl_up_sync(0xffffffffu, w, o);
            if (lane >= o) w += y;
        }
        wsum[lane] = w;
    }
    __syncthreads();
    int incl = x + (warp > 0 ? wsum[warp - 1] : 0);
    if (i < N) g_rowptr[i + 1] = incl;
    if (threadIdx.x == 1023) g_bsum[blockIdx.x] = incl;
}
__global__ void scanB_kernel(int B) {
    if (threadIdx.x == 0) {
        int acc = 0;
        for (int b = 0; b < B; b++) { int v = g_bsum[b]; g_boff[b] = acc; acc += v; }
    }
}
__global__ __launch_bounds__(1024) void scanC_kernel(int N) {
    int i = blockIdx.x * 1024 + threadIdx.x;
    if (i == 0) g_rowptr[0] = 0;
    if (i < N) {
        int r = g_rowptr[i + 1] + g_boff[blockIdx.x];
        g_rowptr[i + 1] = r;
        g_cur[i] = r - g_deg[i];
    }
}
__global__ void scatter_kernel(const void* __restrict__ ei, long long E) {
    long long e = (long long)blockIdx.x * blockDim.x + threadIdx.x;
    if (e >= E) return;
    int is64 = g_is64;
    int src = ld_idx(ei, e, is64);
    int dst = ld_idx(ei, E + e, is64);
    int pos = atomicAdd(&g_cur[dst], 1);
    g_esrc[pos] = src;
}

// ---------------- fused triple SGEMM: FFMA2 with pre-duplicated A ----------
// 128x128x16 tiles, 256 threads, 8x8 acc/thread (8x4 f32x2 pairs),
// double-buffered smem. A stored duplicated (each value twice) so the inner
// loop reads packed f32x2 operands straight from smem (broadcast, no MOVs).
#define TM 128
#define TN 128
#define TK 16

__global__ __launch_bounds__(256) void sgemm3_kernel(
    const float* __restrict__ A,
    const float* __restrict__ B0, const float* __restrict__ B1,
    const float* __restrict__ B2,
    const float* __restrict__ bias0, const float* __restrict__ bias1,
    const float* __restrict__ bias2,
    float* __restrict__ C0, float* __restrict__ C1, float* __restrict__ C2,
    int M, int K)
{
    const int sel = blockIdx.x >> 1;
    const int n0  = (blockIdx.x & 1) * TN;
    const float* B    = (sel == 0) ? B0 : (sel == 1) ? B1 : B2;
    const float* bias = (sel == 0) ? bias0 : (sel == 1) ? bias1 : bias2;
    float*       C    = (sel == 0) ? C0 : (sel == 1) ? C1 : C2;
    const int m0 = blockIdx.y * TM;

    // As duplicated: [k][2*row] = [k][2*row+1] = A[row][k]; 16KB per buffer
    __shared__ float As[2][TK][TM * 2];
    __shared__ float Bs[2][TK][TN];

    const int tid = threadIdx.x;
    const int tm  = tid >> 4;
    const int tn  = tid & 15;
    const int ar0 = tid >> 2;
    const int akq = (tid & 3) * 4;
    const int br0 = tid >> 5;
    const int bcq = (tid & 31) * 4;

    unsigned long long acc[8][4];
    #pragma unroll
    for (int i = 0; i < 8; i++)
        #pragma unroll
        for (int j = 0; j < 4; j++) acc[i][j] = 0ull;

    float4 ra[2], rb[2];

    #pragma unroll
    for (int it = 0; it < 2; it++) {
        int row = ar0 + it * 64;
        float4 v = make_float4(0.f, 0.f, 0.f, 0.f);
        if (m0 + row < M)
            v = *(const float4*)(A + (long long)(m0 + row) * K + akq);
        As[0][akq + 0][2*row] = v.x; As[0][akq + 0][2*row+1] = v.x;
        As[0][akq + 1][2*row] = v.y; As[0][akq + 1][2*row+1] = v.y;
        As[0][akq + 2][2*row] = v.z; As[0][akq + 2][2*row+1] = v.z;
        As[0][akq + 3][2*row] = v.w; As[0][akq + 3][2*row+1] = v.w;
        int krow = br0 + it * 8;
        float4 w = *(const float4*)(B + (long long)krow * 256 + n0 + bcq);
        *(float4*)&Bs[0][krow][bcq] = w;
    }
    __syncthreads();

    int buf = 0;
    for (int k0 = 0; k0 < K; k0 += TK) {
        const int kn = k0 + TK;
        if (kn < K) {
            #pragma unroll
            for (int it = 0; it < 2; it++) {
                int row = ar0 + it * 64;
                ra[it] = make_float4(0.f, 0.f, 0.f, 0.f);
                if (m0 + row < M)
                    ra[it] = *(const float4*)(A + (long long)(m0 + row) * K + kn + akq);
                int krow = br0 + it * 8;
                rb[it] = *(const float4*)(B + (long long)(kn + krow) * 256 + n0 + bcq);
            }
        }
        #pragma unroll
        for (int k = 0; k < TK; k++) {
            // 8 duplicated a-values = 16 floats = 4 x LDS.128 (quarter-warp broadcast)
            ulonglong2 a01 = *(const ulonglong2*)&As[buf][k][tm * 16];
            ulonglong2 a23 = *(const ulonglong2*)&As[buf][k][tm * 16 + 4];
            ulonglong2 a45 = *(const ulonglong2*)&As[buf][k][tm * 16 + 8];
            ulonglong2 a67 = *(const ulonglong2*)&As[buf][k][tm * 16 + 12];
            unsigned long long ad[8] = {a01.x, a01.y, a23.x, a23.y,
                                        a45.x, a45.y, a67.x, a67.y};
            ulonglong2 b01 = *(const ulonglong2*)&Bs[buf][k][tn * 8];
            ulonglong2 b23 = *(const ulonglong2*)&Bs[buf][k][tn * 8 + 4];
            unsigned long long bp[4] = {b01.x, b01.y, b23.x, b23.y};
            #pragma unroll
            for (int i = 0; i < 8; i++)
                #pragma unroll
                for (int j = 0; j < 4; j++)
                    acc[i][j] = f32x2_fma(ad[i], bp[j], acc[i][j]);
        }
        if (kn < K) {
            int nb = buf ^ 1;
            #pragma unroll
            for (int it = 0; it < 2; it++) {
                int row = ar0 + it * 64;
                As[nb][akq + 0][2*row] = ra[it].x; As[nb][akq + 0][2*row+1] = ra[it].x;
                As[nb][akq + 1][2*row] = ra[it].y; As[nb][akq + 1][2*row+1] = ra[it].y;
                As[nb][akq + 2][2*row] = ra[it].z; As[nb][akq + 2][2*row+1] = ra[it].z;
                As[nb][akq + 3][2*row] = ra[it].w; As[nb][akq + 3][2*row+1] = ra[it].w;
                int krow = br0 + it * 8;
                *(float4*)&Bs[nb][krow][bcq] = rb[it];
            }
        }
        __syncthreads();
        buf ^= 1;
    }

    const int c0 = n0 + tn * 8;
    ulonglong2 bias01 = *(const ulonglong2*)(bias + c0);
    ulonglong2 bias23 = *(const ulonglong2*)(bias + c0 + 4);
    unsigned long long bp[4] = {bias01.x, bias01.y, bias23.x, bias23.y};
    #pragma unroll
    for (int i = 0; i < 8; i++) {
        int m = m0 + tm * 8 + i;
        if (m < M) {
            ulonglong2 o01, o23;
            o01.x = f32x2_add(acc[i][0], bp[0]);
            o01.y = f32x2_add(acc[i][1], bp[1]);
            o23.x = f32x2_add(acc[i][2], bp[2]);
            o23.y = f32x2_add(acc[i][3], bp[3]);
            *(ulonglong2*)(C + (long long)m * 256 + c0)     = o01;
            *(ulonglong2*)(C + (long long)m * 256 + c0 + 4) = o23;
        }
    }
}

// ------- fused conv1 CSR + softmax + skip + LN + ELU + conv2 projection ----
// One warp per dst node; software-pipelined xl gathers.
__global__ __launch_bounds__(256) void conv1_csr_kernel(
    const float* __restrict__ att1, const float* __restrict__ bias1,
    const float* __restrict__ gamma, const float* __restrict__ beta,
    const float* __restrict__ W2l, const float* __restrict__ b2l,
    const float* __restrict__ W2r, const float* __restrict__ b2r,
    const float* __restrict__ att2, int N)
{
    const int n = blockIdx.x * 8 + (threadIdx.x >> 5);
    const int lane = threadIdx.x & 31;
    if (n >= N) return;

    float attv[8];
    {
        float4 a0 = *(const float4*)(att1 + lane * 8);
        float4 a1 = *(const float4*)(att1 + lane * 8 + 4);
        attv[0]=a0.x; attv[1]=a0.y; attv[2]=a0.z; attv[3]=a0.w;
        attv[4]=a1.x; attv[5]=a1.y; attv[6]=a1.z; attv[7]=a1.w;
    }
    float xr[8];
    {
        const float* p = g_XR1 + (long long)n * HCc + lane * 8;
        float4 r0 = *(const float4*)p;
        float4 r1 = *(const float4*)(p + 4);
        xr[0]=r0.x; xr[1]=r0.y; xr[2]=r0.z; xr[3]=r0.w;
        xr[4]=r1.x; xr[5]=r1.y; xr[6]=r1.z; xr[7]=r1.w;
    }

    float acc[8], den;
    const int row0 = g_rowptr[n];
    const int row1 = g_rowptr[n + 1];

    // issue first edge's gather before processing the self loop
    float4 nl0, nl1;
    int src0 = (row0 < row1) ? g_esrc[row0] : 0;
    {
        const float* p = g_XL1 + (long long)src0 * HCc + lane * 8;
        nl0 = *(const float4*)p;
        nl1 = *(const float4*)(p + 4);
    }

    // self-loop
    {
        const float* p = g_XL1 + (long long)n * HCc + lane * 8;
        float4 l0 = *(const float4*)p;
        float4 l1 = *(const float4*)(p + 4);
        float xl[8] = {l0.x,l0.y,l0.z,l0.w,l1.x,l1.y,l1.z,l1.w};
        float s = 0.f;
        #pragma unroll
        for (int j = 0; j < 8; j++) {
            float e = xl[j] + xr[j];
            e = e > 0.f ? e : NEG * e;
            s = fmaf(e, attv[j], s);
        }
        s += __shfl_xor_sync(0xffffffffu, s, 1);
        s += __shfl_xor_sync(0xffffffffu, s, 2);
        s += __shfl_xor_sync(0xffffffffu, s, 4);
        float ex = expf(s);
        den = ex;
        #pragma unroll
        for (int j = 0; j < 8; j++) acc[j] = ex * xl[j];
    }

    for (int i = row0; i < row1; i++) {
        // current edge data (already in flight / registers)
        float xl[8] = {nl0.x,nl0.y,nl0.z,nl0.w,nl1.x,nl1.y,nl1.z,nl1.w};
        // issue next edge's gather before the serial reduce/exp chain
        if (i + 1 < row1) {
            int srcn = g_esrc[i + 1];
            const float* p = g_XL1 + (long long)srcn * HCc + lane * 8;
            nl0 = *(const float4*)p;
            nl1 = *(const float4*)(p + 4);
        }
        float s = 0.f;
        #pragma unroll
        for (int j = 0; j < 8; j++) {
            float e = xl[j] + xr[j];
            e = e > 0.f ? e : NEG * e;
            s = fmaf(e, attv[j], s);
        }
        s += __shfl_xor_sync(0xffffffffu, s, 1);
        s += __shfl_xor_sync(0xffffffffu, s, 2);
        s += __shfl_xor_sync(0xffffffffu, s, 4);
        float ex = expf(s);
        den += ex;
        #pragma unroll
        for (int j = 0; j < 8; j++) acc[j] = fmaf(ex, xl[j], acc[j]);
    }

    const float dinv = 1.0f / den;
    float v[8];
    {
        const float* sp = g_SKIP + (long long)n * HCc + lane * 8;
        float4 s0 = *(const float4*)sp;
        float4 s1 = *(const float4*)(sp + 4);
        float4 b0 = *(const float4*)(bias1 + lane * 8);
        float4 b1 = *(const float4*)(bias1 + lane * 8 + 4);
        float sk[8] = {s0.x,s0.y,s0.z,s0.w,s1.x,s1.y,s1.z,s1.w};
        float bb[8] = {b0.x,b0.y,b0.z,b0.w,b1.x,b1.y,b1.z,b1.w};
        #pragma unroll
        for (int j = 0; j < 8; j++) v[j] = acc[j] * dinv + bb[j] + sk[j];
    }

    float t = 0.f;
    #pragma unroll
    for (int j = 0; j < 8; j++) t += v[j];
    #pragma unroll
    for (int o = 16; o > 0; o >>= 1) t += __shfl_xor_sync(0xffffffffu, t, o);
    const float mu = t * (1.0f / 256.0f);
    float t2 = 0.f;
    #pragma unroll
    for (int j = 0; j < 8; j++) { float d = v[j] - mu; t2 = fmaf(d, d, t2); }
    #pragma unroll
    for (int o = 16; o > 0; o >>= 1) t2 += __shfl_xor_sync(0xffffffffu, t2, o);
    const float rstd = rsqrtf(t2 * (1.0f / 256.0f) + 1e-5f);

    float h[8];
    {
        float4 g0 = *(const float4*)(gamma + lane * 8);
        float4 g1 = *(const float4*)(gamma + lane * 8 + 4);
        float4 e0 = *(const float4*)(beta + lane * 8);
        float4 e1 = *(const float4*)(beta + lane * 8 + 4);
        float gg[8] = {g0.x,g0.y,g0.z,g0.w,g1.x,g1.y,g1.z,g1.w};
        float be[8] = {e0.x,e0.y,e0.z,e0.w,e1.x,e1.y,e1.z,e1.w};
        #pragma unroll
        for (int j = 0; j < 8; j++) {
            float hh = (v[j] - mu) * rstd * gg[j] + be[j];
            h[j] = hh > 0.f ? hh : expm1f(hh);
        }
    }

    float p0 = 0.f, p1 = 0.f, p2 = 0.f, p3 = 0.f;
    {
        const float* wl = W2l + lane * 16;
        const float* wr = W2r + lane * 16;
        float4 wl0 = *(const float4*)wl;
        float4 wl1 = *(const float4*)(wl + 4);
        float4 wl2 = *(const float4*)(wl + 8);
        float4 wl3 = *(const float4*)(wl + 12);
        float4 wr0 = *(const float4*)wr;
        float4 wr1 = *(const float4*)(wr + 4);
        float4 wr2 = *(const float4*)(wr + 8);
        float4 wr3 = *(const float4*)(wr + 12);
        float wlv[16] = {wl0.x,wl0.y,wl0.z,wl0.w, wl1.x,wl1.y,wl1.z,wl1.w,
                         wl2.x,wl2.y,wl2.z,wl2.w, wl3.x,wl3.y,wl3.z,wl3.w};
        float wrv[16] = {wr0.x,wr0.y,wr0.z,wr0.w, wr1.x,wr1.y,wr1.z,wr1.w,
                         wr2.x,wr2.y,wr2.z,wr2.w, wr3.x,wr3.y,wr3.z,wr3.w};
        #pragma unroll
        for (int j = 0; j < 8; j++) {
            p0 = fmaf(h[j], wlv[2 * j + 0], p0);
            p1 = fmaf(h[j], wlv[2 * j + 1], p1);
            p2 = fmaf(h[j], wrv[2 * j + 0], p2);
            p3 = fmaf(h[j], wrv[2 * j + 1], p3);
        }
    }
    #pragma unroll
    for (int o = 16; o > 0; o >>= 1) {
        p0 += __shfl_xor_sync(0xffffffffu, p0, o);
        p1 += __shfl_xor_sync(0xffffffffu, p1, o);
        p2 += __shfl_xor_sync(0xffffffffu, p2, o);
        p3 += __shfl_xor_sync(0xffffffffu, p3, o);
    }
    if (lane == 0) {
        float2 xl2, xr2;
        xl2.x = p0 + b2l[0]; xl2.y = p1 + b2l[1];
        xr2.x = p2 + b2r[0]; xr2.y = p3 + b2r[1];
        *(float2*)&g_XL2[n * 2] = xl2;
        *(float2*)&g_XR2[n * 2] = xr2;
    }
}

// ------------- conv2 CSR + final output (one thread per node) -------------
__global__ void conv2_csr_kernel(const float* __restrict__ att2,
                                 const float* __restrict__ bias2,
                                 float* __restrict__ out, int N) {
    int n = blockIdx.x * blockDim.x + threadIdx.x;
    if (n >= N) return;
    const float a0 = att2[0], a1 = att2[1];
    float2 xls = *(const float2*)&g_XL2[n * 2];
    float2 xr  = *(const float2*)&g_XR2[n * 2];
    float e0 = xls.x + xr.x; e0 = e0 > 0.f ? e0 : NEG * e0;
    float e1 = xls.y + xr.y; e1 = e1 > 0.f ? e1 : NEG * e1;
    float ex = expf(fmaf(e0, a0, e1 * a1));
    float den = ex, s0 = ex * xls.x, s1 = ex * xls.y;
    const int row0 = g_rowptr[n], row1 = g_rowptr[n + 1];
    for (int i = row0; i < row1; i++) {
        int src = g_esrc[i];
        float2 xl = *(const float2*)&g_XL2[src * 2];
        float f0 = xl.x + xr.x; f0 = f0 > 0.f ? f0 : NEG * f0;
        float f1 = xl.y + xr.y; f1 = f1 > 0.f ? f1 : NEG * f1;
        float exi = expf(fmaf(f0, a0, f1 * a1));
        den += exi;
        s0 = fmaf(exi, xl.x, s0);
        s1 = fmaf(exi, xl.y, s1);
    }
    float dinv = 1.0f / den;
    float2 o;
    o.x = s0 * dinv + bias2[0];
    o.y = s1 * dinv + bias2[1];
    *(float2*)(out + n * 2) = o;
}

// ---------------------------------------------------------------------------
extern "C" void kernel_launch(void* const* d_in, const int* in_sizes, int n_in,
                              void* d_out, int out_size) {
    const float* x     = (const float*)d_in[0];
    const void*  ei    = d_in[1];
    const float* W1l   = (const float*)d_in[2];
    const float* b1l   = (const float*)d_in[3];
    const float* W1r   = (const float*)d_in[4];
    const float* b1r   = (const float*)d_in[5];
    const float* att1  = (const float*)d_in[6];
    const float* bias1 = (const float*)d_in[7];
    const float* W2l   = (const float*)d_in[8];
    const float* b2l   = (const float*)d_in[9];
    const float* W2r   = (const float*)d_in[10];
    const float* b2r   = (const float*)d_in[11];
    const float* att2  = (const float*)d_in[12];
    const float* bias2 = (const float*)d_in[13];
    const float* Wskip = (const float*)d_in[14];
    const float* bskip = (const float*)d_in[15];
    const float* gamma = (const float*)d_in[16];
    const float* beta  = (const float*)d_in[17];
    float* out = (float*)d_out;

    const int       N = in_sizes[0] / DIN;            // 50000
    const long long E = (long long)in_sizes[1] / 2;   // 800000

    float *dXL1, *dXR1, *dSKIP;
    cudaGetSymbolAddress((void**)&dXL1, g_XL1);
    cudaGetSymbolAddress((void**)&dXR1, g_XR1);
    cudaGetSymbolAddress((void**)&dSKIP, g_SKIP);

    detect_idx_kernel<<<1, 1>>>((const unsigned int*)ei);

    // CSR build
    const int SB = (N + 1023) / 1024;
    zero_deg_kernel<<<(N + 255) / 256, 256>>>(N);
    hist_kernel<<<(int)((E + 255) / 256), 256>>>(ei, E);
    scanA_kernel<<<SB, 1024>>>(N);
    scanB_kernel<<<1, 32>>>(SB);
    scanC_kernel<<<SB, 1024>>>(N);
    scatter_kernel<<<(int)((E + 255) / 256), 256>>>(ei, E);

    // fused triple GEMM (FFMA2, pre-duplicated A)
    dim3 gg(6, (N + TM - 1) / TM);
    sgemm3_kernel<<<gg, 256>>>(x, W1l, W1r, Wskip, b1l, b1r, bskip,
                               dXL1, dXR1, dSKIP, N, DIN);

    // fused conv1 + epilogue (warp per node, pipelined gathers, no atomics)
    conv1_csr_kernel<<<(N + 7) / 8, 256>>>(att1, bias1, gamma, beta,
                                           W2l, b2l, W2r, b2r, att2, N);

    // conv2 + final output
    conv2_csr_kernel<<<(N + 255) / 256, 256>>>(att2, bias2, out, N);
}

// round 7
// speedup vs baseline: 1.1442x; 1.1442x over previous
#include <cuda_runtime.h>
#include <math.h>
#include <stdint.h>

// Problem constants
#define DIN   256
#define HCc   256
#define NEG   0.2f
#define MAXN  50000
#define MAXE  1000000

// ---------------- scratch (static device globals) --------------------------
__device__ float g_XL1[(long long)MAXN * HCc];
__device__ float g_XR1[(long long)MAXN * HCc];
__device__ float g_SKIP[(long long)MAXN * HCc];
__device__ float g_XL2[MAXN * 2];
__device__ float g_XR2[MAXN * 2];
__device__ int   g_deg[MAXN];
__device__ int   g_rowptr[MAXN + 1];
__device__ int   g_cur[MAXN];
__device__ int   g_esrc[MAXE];
__device__ int   g_bsum[64];
__device__ int   g_boff[64];
__device__ int   g_is64;

// ---------------- packed f32x2 helpers --------------------------------------
__device__ __forceinline__ unsigned long long f32x2_dup(float a) {
    unsigned long long d;
    asm("mov.b64 %0, {%1, %1};" : "=l"(d) : "r"(__float_as_uint(a)));
    return d;
}
__device__ __forceinline__ unsigned long long f32x2_fma(unsigned long long a,
                                                        unsigned long long b,
                                                        unsigned long long c) {
    unsigned long long d;
    asm("fma.rn.f32x2 %0, %1, %2, %3;" : "=l"(d) : "l"(a), "l"(b), "l"(c));
    return d;
}
__device__ __forceinline__ unsigned long long f32x2_add(unsigned long long a,
                                                        unsigned long long b) {
    unsigned long long d;
    asm("add.rn.f32x2 %0, %1, %2;" : "=l"(d) : "l"(a), "l"(b));
    return d;
}

// ---------------- dtype detection for edge_index (int32 vs int64) ---------
__global__ void detect_idx_kernel(const unsigned int* __restrict__ w) {
    int ok = 1;
    #pragma unroll
    for (int i = 0; i < 32; i++) {
        if (w[2 * i + 1] != 0u) { ok = 0; break; }
    }
    g_is64 = ok;
}
__device__ __forceinline__ int ld_idx(const void* ei, long long pos, int is64) {
    if (is64) return (int)(((const long long*)ei)[pos]);
    return ((const int*)ei)[pos];
}

// ---------------- CSR build -------------------------------------------------
__global__ void zero_deg_kernel(int N) {
    int i = blockIdx.x * blockDim.x + threadIdx.x;
    if (i < N) g_deg[i] = 0;
}
__global__ void hist_kernel(const void* __restrict__ ei, long long E) {
    long long e = (long long)blockIdx.x * blockDim.x + threadIdx.x;
    if (e >= E) return;
    int dst = ld_idx(ei, E + e, g_is64);
    atomicAdd(&g_deg[dst], 1);
}
__global__ __launch_bounds__(1024) void scanA_kernel(int N) {
    __shared__ int wsum[32];
    const int lane = threadIdx.x & 31, warp = threadIdx.x >> 5;
    int i = blockIdx.x * 1024 + threadIdx.x;
    int v = (i < N) ? g_deg[i] : 0;
    int x = v;
    #pragma unroll
    for (int o = 1; o < 32; o <<= 1) {
        int y = __shfl_up_sync(0xffffffffu, x, o);
        if (lane >= o) x += y;
    }
    if (lane == 31) wsum[warp] = x;
    __syncthreads();
    if (warp == 0) {
        int w = wsum[lane];
        #pragma unroll
        for (int o = 1; o < 32; o <<= 1) {
            int y = __shfl_up_sync(0xffffffffu, w, o);
            if (lane >= o) w += y;
        }
        wsum[lane] = w;
    }
    __syncthreads();
    int incl = x + (warp > 0 ? wsum[warp - 1] : 0);
    if (i < N) g_rowptr[i + 1] = incl;
    if (threadIdx.x == 1023) g_bsum[blockIdx.x] = incl;
}
__global__ void scanB_kernel(int B) {
    if (threadIdx.x == 0) {
        int acc = 0;
        for (int b = 0; b < B; b++) { int v = g_bsum[b]; g_boff[b] = acc; acc += v; }
    }
}
__global__ __launch_bounds__(1024) void scanC_kernel(int N) {
    int i = blockIdx.x * 1024 + threadIdx.x;
    if (i == 0) g_rowptr[0] = 0;
    if (i < N) {
        int r = g_rowptr[i + 1] + g_boff[blockIdx.x];
        g_rowptr[i + 1] = r;
        g_cur[i] = r - g_deg[i];
    }
}
__global__ void scatter_kernel(const void* __restrict__ ei, long long E) {
    long long e = (long long)blockIdx.x * blockDim.x + threadIdx.x;
    if (e >= E) return;
    int is64 = g_is64;
    int src = ld_idx(ei, e, is64);
    int dst = ld_idx(ei, E + e, is64);
    int pos = atomicAdd(&g_cur[dst], 1);
    g_esrc[pos] = src;
}

// ---------------- fused triple SGEMM with packed FFMA2 (R5 version) --------
#define TM 128
#define TN 128
#define TK 16

__global__ __launch_bounds__(256) void sgemm3_kernel(
    const float* __restrict__ A,
    const float* __restrict__ B0, const float* __restrict__ B1,
    const float* __restrict__ B2,
    const float* __restrict__ bias0, const float* __restrict__ bias1,
    const float* __restrict__ bias2,
    float* __restrict__ C0, float* __restrict__ C1, float* __restrict__ C2,
    int M, int K)
{
    const int sel = blockIdx.x >> 1;
    const int n0  = (blockIdx.x & 1) * TN;
    const float* B    = (sel == 0) ? B0 : (sel == 1) ? B1 : B2;
    const float* bias = (sel == 0) ? bias0 : (sel == 1) ? bias1 : bias2;
    float*       C    = (sel == 0) ? C0 : (sel == 1) ? C1 : C2;
    const int m0 = blockIdx.y * TM;

    __shared__ float As[2][TK][TM];
    __shared__ float Bs[2][TK][TN];

    const int tid = threadIdx.x;
    const int tm  = tid >> 4;
    const int tn  = tid & 15;
    const int ar0 = tid >> 2;
    const int akq = (tid & 3) * 4;
    const int br0 = tid >> 5;
    const int bcq = (tid & 31) * 4;

    unsigned long long acc[8][4];
    #pragma unroll
    for (int i = 0; i < 8; i++)
        #pragma unroll
        for (int j = 0; j < 4; j++) acc[i][j] = 0ull;

    float4 ra[2], rb[2];

    #pragma unroll
    for (int it = 0; it < 2; it++) {
        int row = ar0 + it * 64;
        float4 v = make_float4(0.f, 0.f, 0.f, 0.f);
        if (m0 + row < M)
            v = *(const float4*)(A + (long long)(m0 + row) * K + akq);
        As[0][akq + 0][row] = v.x; As[0][akq + 1][row] = v.y;
        As[0][akq + 2][row] = v.z; As[0][akq + 3][row] = v.w;
        int krow = br0 + it * 8;
        float4 w = *(const float4*)(B + (long long)krow * 256 + n0 + bcq);
        *(float4*)&Bs[0][krow][bcq] = w;
    }
    __syncthreads();

    int buf = 0;
    for (int k0 = 0; k0 < K; k0 += TK) {
        const int kn = k0 + TK;
        if (kn < K) {
            #pragma unroll
            for (int it = 0; it < 2; it++) {
                int row = ar0 + it * 64;
                ra[it] = make_float4(0.f, 0.f, 0.f, 0.f);
                if (m0 + row < M)
                    ra[it] = *(const float4*)(A + (long long)(m0 + row) * K + kn + akq);
                int krow = br0 + it * 8;
                rb[it] = *(const float4*)(B + (long long)(kn + krow) * 256 + n0 + bcq);
            }
        }
        #pragma unroll
        for (int k = 0; k < TK; k++) {
            float4 a0 = *(const float4*)&As[buf][k][tm * 8];
            float4 a1 = *(const float4*)&As[buf][k][tm * 8 + 4];
            ulonglong2 b01 = *(const ulonglong2*)&Bs[buf][k][tn * 8];
            ulonglong2 b23 = *(const ulonglong2*)&Bs[buf][k][tn * 8 + 4];
            unsigned long long bp[4] = {b01.x, b01.y, b23.x, b23.y};
            unsigned long long ad[8];
            ad[0] = f32x2_dup(a0.x); ad[1] = f32x2_dup(a0.y);
            ad[2] = f32x2_dup(a0.z); ad[3] = f32x2_dup(a0.w);
            ad[4] = f32x2_dup(a1.x); ad[5] = f32x2_dup(a1.y);
            ad[6] = f32x2_dup(a1.z); ad[7] = f32x2_dup(a1.w);
            #pragma unroll
            for (int i = 0; i < 8; i++)
                #pragma unroll
                for (int j = 0; j < 4; j++)
                    acc[i][j] = f32x2_fma(ad[i], bp[j], acc[i][j]);
        }
        if (kn < K) {
            int nb = buf ^ 1;
            #pragma unroll
            for (int it = 0; it < 2; it++) {
                int row = ar0 + it * 64;
                As[nb][akq + 0][row] = ra[it].x; As[nb][akq + 1][row] = ra[it].y;
                As[nb][akq + 2][row] = ra[it].z; As[nb][akq + 3][row] = ra[it].w;
                int krow = br0 + it * 8;
                *(float4*)&Bs[nb][krow][bcq] = rb[it];
            }
        }
        __syncthreads();
        buf ^= 1;
    }

    const int c0 = n0 + tn * 8;
    ulonglong2 bias01 = *(const ulonglong2*)(bias + c0);
    ulonglong2 bias23 = *(const ulonglong2*)(bias + c0 + 4);
    unsigned long long bp[4] = {bias01.x, bias01.y, bias23.x, bias23.y};
    #pragma unroll
    for (int i = 0; i < 8; i++) {
        int m = m0 + tm * 8 + i;
        if (m < M) {
            ulonglong2 o01, o23;
            o01.x = f32x2_add(acc[i][0], bp[0]);
            o01.y = f32x2_add(acc[i][1], bp[1]);
            o23.x = f32x2_add(acc[i][2], bp[2]);
            o23.y = f32x2_add(acc[i][3], bp[3]);
            *(ulonglong2*)(C + (long long)m * 256 + c0)     = o01;
            *(ulonglong2*)(C + (long long)m * 256 + c0 + 4) = o23;
        }
    }
}

// ------- fused conv1 CSR + softmax + skip + LN + ELU + conv2 projection ----
// One warp per dst node. Edge loop unrolled x2 with independent chains.
__global__ __launch_bounds__(256) void conv1_csr_kernel(
    const float* __restrict__ att1, const float* __restrict__ bias1,
    const float* __restrict__ gamma, const float* __restrict__ beta,
    const float* __restrict__ W2l, const float* __restrict__ b2l,
    const float* __restrict__ W2r, const float* __restrict__ b2r,
    const float* __restrict__ att2, int N)
{
    const int n = blockIdx.x * 8 + (threadIdx.x >> 5);
    const int lane = threadIdx.x & 31;
    if (n >= N) return;

    float attv[8];
    {
        float4 a0 = *(const float4*)(att1 + lane * 8);
        float4 a1 = *(const float4*)(att1 + lane * 8 + 4);
        attv[0]=a0.x; attv[1]=a0.y; attv[2]=a0.z; attv[3]=a0.w;
        attv[4]=a1.x; attv[5]=a1.y; attv[6]=a1.z; attv[7]=a1.w;
    }
    float xr[8];
    {
        const float* p = g_XR1 + (long long)n * HCc + lane * 8;
        float4 r0 = *(const float4*)p;
        float4 r1 = *(const float4*)(p + 4);
        xr[0]=r0.x; xr[1]=r0.y; xr[2]=r0.z; xr[3]=r0.w;
        xr[4]=r1.x; xr[5]=r1.y; xr[6]=r1.z; xr[7]=r1.w;
    }

    float acc[8], den;
    // self-loop
    {
        const float* p = g_XL1 + (long long)n * HCc + lane * 8;
        float4 l0 = *(const float4*)p;
        float4 l1 = *(const float4*)(p + 4);
        float xl[8] = {l0.x,l0.y,l0.z,l0.w,l1.x,l1.y,l1.z,l1.w};
        float s = 0.f;
        #pragma unroll
        for (int j = 0; j < 8; j++) {
            float e = xl[j] + xr[j];
            e = e > 0.f ? e : NEG * e;
            s = fmaf(e, attv[j], s);
        }
        s += __shfl_xor_sync(0xffffffffu, s, 1);
        s += __shfl_xor_sync(0xffffffffu, s, 2);
        s += __shfl_xor_sync(0xffffffffu, s, 4);
        float ex = expf(s);
        den = ex;
        #pragma unroll
        for (int j = 0; j < 8; j++) acc[j] = ex * xl[j];
    }

    const int row0 = g_rowptr[n];
    const int row1 = g_rowptr[n + 1];
    int i = row0;
    // pairs of edges: independent gather + reduce + exp chains
    for (; i + 1 < row1; i += 2) {
        int srcA = g_esrc[i];
        int srcB = g_esrc[i + 1];
        const float* pA = g_XL1 + (long long)srcA * HCc + lane * 8;
        const float* pB = g_XL1 + (long long)srcB * HCc + lane * 8;
        float4 a0 = *(const float4*)pA;
        float4 a1 = *(const float4*)(pA + 4);
        float4 b0 = *(const float4*)pB;
        float4 b1 = *(const float4*)(pB + 4);
        float xlA[8] = {a0.x,a0.y,a0.z,a0.w,a1.x,a1.y,a1.z,a1.w};
        float xlB[8] = {b0.x,b0.y,b0.z,b0.w,b1.x,b1.y,b1.z,b1.w};
        float sA = 0.f, sB = 0.f;
        #pragma unroll
        for (int j = 0; j < 8; j++) {
            float eA = xlA[j] + xr[j];
            float eB = xlB[j] + xr[j];
            eA = eA > 0.f ? eA : NEG * eA;
            eB = eB > 0.f ? eB : NEG * eB;
            sA = fmaf(eA, attv[j], sA);
            sB = fmaf(eB, attv[j], sB);
        }
        #pragma unroll
        for (int o = 1; o <= 4; o <<= 1) {
            sA += __shfl_xor_sync(0xffffffffu, sA, o);
            sB += __shfl_xor_sync(0xffffffffu, sB, o);
        }
        float exA = expf(sA);
        float exB = expf(sB);
        den += exA + exB;
        #pragma unroll
        for (int j = 0; j < 8; j++) {
            acc[j] = fmaf(exA, xlA[j], acc[j]);
            acc[j] = fmaf(exB, xlB[j], acc[j]);
        }
    }
    // tail edge
    if (i < row1) {
        int src = g_esrc[i];
        const float* p = g_XL1 + (long long)src * HCc + lane * 8;
        float4 l0 = *(const float4*)p;
        float4 l1 = *(const float4*)(p + 4);
        float xl[8] = {l0.x,l0.y,l0.z,l0.w,l1.x,l1.y,l1.z,l1.w};
        float s = 0.f;
        #pragma unroll
        for (int j = 0; j < 8; j++) {
            float e = xl[j] + xr[j];
            e = e > 0.f ? e : NEG * e;
            s = fmaf(e, attv[j], s);
        }
        s += __shfl_xor_sync(0xffffffffu, s, 1);
        s += __shfl_xor_sync(0xffffffffu, s, 2);
        s += __shfl_xor_sync(0xffffffffu, s, 4);
        float ex = expf(s);
        den += ex;
        #pragma unroll
        for (int j = 0; j < 8; j++) acc[j] = fmaf(ex, xl[j], acc[j]);
    }

    const float dinv = 1.0f / den;
    float v[8];
    {
        const float* sp = g_SKIP + (long long)n * HCc + lane * 8;
        float4 s0 = *(const float4*)sp;
        float4 s1 = *(const float4*)(sp + 4);
        float4 b0 = *(const float4*)(bias1 + lane * 8);
        float4 b1 = *(const float4*)(bias1 + lane * 8 + 4);
        float sk[8] = {s0.x,s0.y,s0.z,s0.w,s1.x,s1.y,s1.z,s1.w};
        float bb[8] = {b0.x,b0.y,b0.z,b0.w,b1.x,b1.y,b1.z,b1.w};
        #pragma unroll
        for (int j = 0; j < 8; j++) v[j] = acc[j] * dinv + bb[j] + sk[j];
    }

    float t = 0.f;
    #pragma unroll
    for (int j = 0; j < 8; j++) t += v[j];
    #pragma unroll
    for (int o = 16; o > 0; o >>= 1) t += __shfl_xor_sync(0xffffffffu, t, o);
    const float mu = t * (1.0f / 256.0f);
    float t2 = 0.f;
    #pragma unroll
    for (int j = 0; j < 8; j++) { float d = v[j] - mu; t2 = fmaf(d, d, t2); }
    #pragma unroll
    for (int o = 16; o > 0; o >>= 1) t2 += __shfl_xor_sync(0xffffffffu, t2, o);
    const float rstd = rsqrtf(t2 * (1.0f / 256.0f) + 1e-5f);

    float h[8];
    {
        float4 g0 = *(const float4*)(gamma + lane * 8);
        float4 g1 = *(const float4*)(gamma + lane * 8 + 4);
        float4 e0 = *(const float4*)(beta + lane * 8);
        float4 e1 = *(const float4*)(beta + lane * 8 + 4);
        float gg[8] = {g0.x,g0.y,g0.z,g0.w,g1.x,g1.y,g1.z,g1.w};
        float be[8] = {e0.x,e0.y,e0.z,e0.w,e1.x,e1.y,e1.z,e1.w};
        #pragma unroll
        for (int j = 0; j < 8; j++) {
            float hh = (v[j] - mu) * rstd * gg[j] + be[j];
            h[j] = hh > 0.f ? hh : expm1f(hh);
        }
    }

    float p0 = 0.f, p1 = 0.f, p2 = 0.f, p3 = 0.f;
    {
        const float* wl = W2l + lane * 16;
        const float* wr = W2r + lane * 16;
        float4 wl0 = *(const float4*)wl;
        float4 wl1 = *(const float4*)(wl + 4);
        float4 wl2 = *(const float4*)(wl + 8);
        float4 wl3 = *(const float4*)(wl + 12);
        float4 wr0 = *(const float4*)wr;
        float4 wr1 = *(const float4*)(wr + 4);
        float4 wr2 = *(const float4*)(wr + 8);
        float4 wr3 = *(const float4*)(wr + 12);
        float wlv[16] = {wl0.x,wl0.y,wl0.z,wl0.w, wl1.x,wl1.y,wl1.z,wl1.w,
                         wl2.x,wl2.y,wl2.z,wl2.w, wl3.x,wl3.y,wl3.z,wl3.w};
        float wrv[16] = {wr0.x,wr0.y,wr0.z,wr0.w, wr1.x,wr1.y,wr1.z,wr1.w,
                         wr2.x,wr2.y,wr2.z,wr2.w, wr3.x,wr3.y,wr3.z,wr3.w};
        #pragma unroll
        for (int j = 0; j < 8; j++) {
            p0 = fmaf(h[j], wlv[2 * j + 0], p0);
            p1 = fmaf(h[j], wlv[2 * j + 1], p1);
            p2 = fmaf(h[j], wrv[2 * j + 0], p2);
            p3 = fmaf(h[j], wrv[2 * j + 1], p3);
        }
    }
    #pragma unroll
    for (int o = 16; o > 0; o >>= 1) {
        p0 += __shfl_xor_sync(0xffffffffu, p0, o);
        p1 += __shfl_xor_sync(0xffffffffu, p1, o);
        p2 += __shfl_xor_sync(0xffffffffu, p2, o);
        p3 += __shfl_xor_sync(0xffffffffu, p3, o);
    }
    if (lane == 0) {
        float2 xl2, xr2;
        xl2.x = p0 + b2l[0]; xl2.y = p1 + b2l[1];
        xr2.x = p2 + b2r[0]; xr2.y = p3 + b2r[1];
        *(float2*)&g_XL2[n * 2] = xl2;
        *(float2*)&g_XR2[n * 2] = xr2;
    }
}

// ------------- conv2 CSR + final output (one thread per node) -------------
__global__ void conv2_csr_kernel(const float* __restrict__ att2,
                                 const float* __restrict__ bias2,
                                 float* __restrict__ out, int N) {
    int n = blockIdx.x * blockDim.x + threadIdx.x;
    if (n >= N) return;
    const float a0 = att2[0], a1 = att2[1];
    float2 xls = *(const float2*)&g_XL2[n * 2];
    float2 xr  = *(const float2*)&g_XR2[n * 2];
    float e0 = xls.x + xr.x; e0 = e0 > 0.f ? e0 : NEG * e0;
    float e1 = xls.y + xr.y; e1 = e1 > 0.f ? e1 : NEG * e1;
    float ex = expf(fmaf(e0, a0, e1 * a1));
    float den = ex, s0 = ex * xls.x, s1 = ex * xls.y;
    const int row0 = g_rowptr[n], row1 = g_rowptr[n + 1];
    for (int i = row0; i < row1; i++) {
        int src = g_esrc[i];
        float2 xl = *(const float2*)&g_XL2[src * 2];
        float f0 = xl.x + xr.x; f0 = f0 > 0.f ? f0 : NEG * f0;
        float f1 = xl.y + xr.y; f1 = f1 > 0.f ? f1 : NEG * f1;
        float exi = expf(fmaf(f0, a0, f1 * a1));
        den += exi;
        s0 = fmaf(exi, xl.x, s0);
        s1 = fmaf(exi, xl.y, s1);
    }
    float dinv = 1.0f / den;
    float2 o;
    o.x = s0 * dinv + bias2[0];
    o.y = s1 * dinv + bias2[1];
    *(float2*)(out + n * 2) = o;
}

// ---------------------------------------------------------------------------
extern "C" void kernel_launch(void* const* d_in, const int* in_sizes, int n_in,
                              void* d_out, int out_size) {
    const float* x     = (const float*)d_in[0];
    const void*  ei    = d_in[1];
    const float* W1l   = (const float*)d_in[2];
    const float* b1l   = (const float*)d_in[3];
    const float* W1r   = (const float*)d_in[4];
    const float* b1r   = (const float*)d_in[5];
    const float* att1  = (const float*)d_in[6];
    const float* bias1 = (const float*)d_in[7];
    const float* W2l   = (const float*)d_in[8];
    const float* b2l   = (const float*)d_in[9];
    const float* W2r   = (const float*)d_in[10];
    const float* b2r   = (const float*)d_in[11];
    const float* att2  = (const float*)d_in[12];
    const float* bias2 = (const float*)d_in[13];
    const float* Wskip = (const float*)d_in[14];
    const float* bskip = (const float*)d_in[15];
    const float* gamma = (const float*)d_in[16];
    const float* beta  = (const float*)d_in[17];
    float* out = (float*)d_out;

    const int       N = in_sizes[0] / DIN;            // 50000
    const long long E = (long long)in_sizes[1] / 2;   // 800000

    float *dXL1, *dXR1, *dSKIP;
    cudaGetSymbolAddress((void**)&dXL1, g_XL1);
    cudaGetSymbolAddress((void**)&dXR1, g_XR1);
    cudaGetSymbolAddress((void**)&dSKIP, g_SKIP);

    detect_idx_kernel<<<1, 1>>>((const unsigned int*)ei);

    // CSR build
    const int SB = (N + 1023) / 1024;
    zero_deg_kernel<<<(N + 255) / 256, 256>>>(N);
    hist_kernel<<<(int)((E + 255) / 256), 256>>>(ei, E);
    scanA_kernel<<<SB, 1024>>>(N);
    scanB_kernel<<<1, 32>>>(SB);
    scanC_kernel<<<SB, 1024>>>(N);
    scatter_kernel<<<(int)((E + 255) / 256), 256>>>(ei, E);

    // fused triple GEMM (FFMA2, R5 layout)
    dim3 gg(6, (N + TM - 1) / TM);
    sgemm3_kernel<<<gg, 256>>>(x, W1l, W1r, Wskip, b1l, b1r, bskip,
                               dXL1, dXR1, dSKIP, N, DIN);

    // fused conv1 + epilogue (warp per node, 2-edge unroll, no atomics)
    conv1_csr_kernel<<<(N + 7) / 8, 256>>>(att1, bias1, gamma, beta,
                                           W2l, b2l, W2r, b2r, att2, N);

    // conv2 + final output
    conv2_csr_kernel<<<(N + 255) / 256, 256>>>(att2, bias2, out, N);
}

// round 8
// speedup vs baseline: 1.3808x; 1.2068x over previous
#include <cuda_runtime.h>
#include <cuda_bf16.h>
#include <math.h>
#include <stdint.h>

// Problem constants
#define DIN   256
#define HCc   256
#define NEG   0.2f
#define MAXN  50000
#define MAXE  1000000

// ---------------- scratch (static device globals) --------------------------
__device__ float g_XL1[(long long)MAXN * HCc];
__device__ float g_XR1[(long long)MAXN * HCc];
__device__ float g_SKIP[(long long)MAXN * HCc];
__device__ float g_XL2[MAXN * 2];
__device__ float g_XR2[MAXN * 2];
__device__ int   g_deg[MAXN];
__device__ int   g_rowptr[MAXN + 1];
__device__ int   g_cur[MAXN];
__device__ int   g_esrc[MAXE];
__device__ int   g_bsum[64];
__device__ int   g_boff[64];
__device__ int   g_is64;
// split-bf16 transposed weights: [sel][N=256][K=256]
__device__ __nv_bfloat16 g_BT_hi[3 * 256 * 256];
__device__ __nv_bfloat16 g_BT_lo[3 * 256 * 256];

// ---------------- small helpers ---------------------------------------------
__device__ __forceinline__ uint32_t smem_u32(const void* p) {
    uint32_t a;
    asm("{ .reg .u64 t; cvta.to.shared.u64 t, %1; cvt.u32.u64 %0, t; }"
        : "=r"(a) : "l"(p));
    return a;
}
__device__ __forceinline__ void ldsm_x4(uint32_t* r, uint32_t addr) {
    asm volatile("ldmatrix.sync.aligned.m8n8.x4.shared.b16 {%0,%1,%2,%3}, [%4];"
        : "=r"(r[0]), "=r"(r[1]), "=r"(r[2]), "=r"(r[3]) : "r"(addr));
}
__device__ __forceinline__ void mma_bf16(float* c, const uint32_t* a,
                                         uint32_t b0, uint32_t b1) {
    asm volatile(
        "mma.sync.aligned.m16n8k16.row.col.f32.bf16.bf16.f32 "
        "{%0,%1,%2,%3}, {%4,%5,%6,%7}, {%8,%9}, {%0,%1,%2,%3};"
        : "+f"(c[0]), "+f"(c[1]), "+f"(c[2]), "+f"(c[3])
        : "r"(a[0]), "r"(a[1]), "r"(a[2]), "r"(a[3]), "r"(b0), "r"(b1));
}

// ---------------- dtype detection for edge_index (int32 vs int64) ---------
__global__ void detect_idx_kernel(const unsigned int* __restrict__ w) {
    int ok = 1;
    #pragma unroll
    for (int i = 0; i < 32; i++) {
        if (w[2 * i + 1] != 0u) { ok = 0; break; }
    }
    g_is64 = ok;
}
__device__ __forceinline__ int ld_idx(const void* ei, long long pos, int is64) {
    if (is64) return (int)(((const long long*)ei)[pos]);
    return ((const int*)ei)[pos];
}

// ---------------- CSR build -------------------------------------------------
__global__ void zero_deg_kernel(int N) {
    int i = blockIdx.x * blockDim.x + threadIdx.x;
    if (i < N) g_deg[i] = 0;
}
__global__ void hist_kernel(const void* __restrict__ ei, long long E) {
    long long e = (long long)blockIdx.x * blockDim.x + threadIdx.x;
    if (e >= E) return;
    int dst = ld_idx(ei, E + e, g_is64);
    atomicAdd(&g_deg[dst], 1);
}
__global__ __launch_bounds__(1024) void scanA_kernel(int N) {
    __shared__ int wsum[32];
    const int lane = threadIdx.x & 31, warp = threadIdx.x >> 5;
    int i = blockIdx.x * 1024 + threadIdx.x;
    int v = (i < N) ? g_deg[i] : 0;
    int x = v;
    #pragma unroll
    for (int o = 1; o < 32; o <<= 1) {
        int y = __shfl_up_sync(0xffffffffu, x, o);
        if (lane >= o) x += y;
    }
    if (lane == 31) wsum[warp] = x;
    __syncthreads();
    if (warp == 0) {
        int w = wsum[lane];
        #pragma unroll
        for (int o = 1; o < 32; o <<= 1) {
            int y = __shfl_up_sync(0xffffffffu, w, o);
            if (lane >= o) w += y;
        }
        wsum[lane] = w;
    }
    __syncthreads();
    int incl = x + (warp > 0 ? wsum[warp - 1] : 0);
    if (i < N) g_rowptr[i + 1] = incl;
    if (threadIdx.x == 1023) g_bsum[blockIdx.x] = incl;
}
__global__ void scanB_kernel(int B) {
    if (threadIdx.x == 0) {
        int acc = 0;
        for (int b = 0; b < B; b++) { int v = g_bsum[b]; g_boff[b] = acc; acc += v; }
    }
}
__global__ __launch_bounds__(1024) void scanC_kernel(int N) {
    int i = blockIdx.x * 1024 + threadIdx.x;
    if (i == 0) g_rowptr[0] = 0;
    if (i < N) {
        int r = g_rowptr[i + 1] + g_boff[blockIdx.x];
        g_rowptr[i + 1] = r;
        g_cur[i] = r - g_deg[i];
    }
}
__global__ void scatter_kernel(const void* __restrict__ ei, long long E) {
    long long e = (long long)blockIdx.x * blockDim.x + threadIdx.x;
    if (e >= E) return;
    int is64 = g_is64;
    int src = ld_idx(ei, e, is64);
    int dst = ld_idx(ei, E + e, is64);
    int pos = atomicAdd(&g_cur[dst], 1);
    g_esrc[pos] = src;
}

// ---------------- B prep: transpose + bf16 split ----------------------------
__global__ void prep_b_kernel(const float* __restrict__ W0,
                              const float* __restrict__ W1,
                              const float* __restrict__ W2) {
    int s = blockIdx.y, k = blockIdx.x, n = threadIdx.x;
    const float* W = (s == 0) ? W0 : (s == 1) ? W1 : W2;
    float v = W[k * 256 + n];
    __nv_bfloat16 hi = __float2bfloat16(v);
    float lo = v - __bfloat162float(hi);
    int idx = (s * 256 + n) * 256 + k;
    g_BT_hi[idx] = hi;
    g_BT_lo[idx] = __float2bfloat16(lo);
}

// ---------------- mma.sync bf16-split triple GEMM ---------------------------
// CTA 128m x 128n x K=256 (16 k-stages). 8 warps, each 64m x 32n.
// D = Ah*Bh + Al*Bh + Ah*Bl (fp32 accum) ~= fp32 GEMM to ~2^-16.
#define PADK 24   // smem row stride in bf16 (48B: 16B-aligned, ldmatrix conflict-free)

__global__ __launch_bounds__(256) void gemm_mma_kernel(
    const float* __restrict__ A,
    const float* __restrict__ bias0, const float* __restrict__ bias1,
    const float* __restrict__ bias2,
    float* __restrict__ C0, float* __restrict__ C1, float* __restrict__ C2,
    int M)
{
    __shared__ __nv_bfloat16 sAh[128 * PADK];
    __shared__ __nv_bfloat16 sAl[128 * PADK];
    __shared__ __nv_bfloat16 sBh[128 * PADK];
    __shared__ __nv_bfloat16 sBl[128 * PADK];

    const int sel = blockIdx.x >> 1;
    const int n0  = (blockIdx.x & 1) * 128;
    const int m0  = blockIdx.y * 128;
    const float* bias = (sel == 0) ? bias0 : (sel == 1) ? bias1 : bias2;
    float*       C    = (sel == 0) ? C0 : (sel == 1) ? C1 : C2;
    const __nv_bfloat16* BTh = g_BT_hi + sel * 65536 + (long long)n0 * 256;
    const __nv_bfloat16* BTl = g_BT_lo + sel * 65536 + (long long)n0 * 256;

    const int tid  = threadIdx.x;
    const int lane = tid & 31;
    const int wid  = tid >> 5;
    const int wm0  = (wid >> 2) * 64;   // warp m offset within tile
    const int wn0  = (wid & 3) * 32;    // warp n offset within tile

    // fill mapping: thread t -> row ar (0..127), k-half ak (0 or 8)
    const int ar = tid >> 1;
    const int ak = (tid & 1) * 8;
    const bool arow_ok = (m0 + ar) < M;
    const float* Ap = A + (long long)(m0 + ar) * 256 + ak;
    __nv_bfloat16* pAh = &sAh[ar * PADK + ak];
    __nv_bfloat16* pAl = &sAl[ar * PADK + ak];
    uint4* pBh = (uint4*)&sBh[ar * PADK + ak];
    uint4* pBl = (uint4*)&sBl[ar * PADK + ak];
    const uint4* gBh = (const uint4*)(BTh + (long long)ar * 256 + ak);
    const uint4* gBl = (const uint4*)(BTl + (long long)ar * 256 + ak);

    // ldmatrix lane addresses (constant across stages; single-buffered smem)
    uint32_t a_h[4], a_l[4], b_h[2], b_l[2];
    {
        int arow = lane & 15;
        int acol = (lane >> 4) * 8;
        #pragma unroll
        for (int fm = 0; fm < 4; fm++) {
            int idx = (wm0 + fm * 16 + arow) * PADK + acol;
            a_h[fm] = smem_u32(&sAh[idx]);
            a_l[fm] = smem_u32(&sAl[idx]);
        }
        int brow = (lane & 7) + (lane >> 4) * 8;
        int bcol = ((lane >> 3) & 1) * 8;
        #pragma unroll
        for (int nb = 0; nb < 2; nb++) {
            int idx = (wn0 + nb * 16 + brow) * PADK + bcol;
            b_h[nb] = smem_u32(&sBh[idx]);
            b_l[nb] = smem_u32(&sBl[idx]);
        }
    }

    float acc[16][4];
    #pragma unroll
    for (int i = 0; i < 16; i++)
        #pragma unroll
        for (int j = 0; j < 4; j++) acc[i][j] = 0.f;

    for (int ks = 0; ks < 256; ks += 16) {
        __syncthreads();   // previous stage fully consumed
        // ---- fill A (fp32 -> bf16 hi/lo) ----
        float4 v0 = make_float4(0.f, 0.f, 0.f, 0.f);
        float4 v1 = make_float4(0.f, 0.f, 0.f, 0.f);
        if (arow_ok) {
            v0 = *(const float4*)(Ap + ks);
            v1 = *(const float4*)(Ap + ks + 4);
        }
        float f[8] = {v0.x, v0.y, v0.z, v0.w, v1.x, v1.y, v1.z, v1.w};
        #pragma unroll
        for (int j = 0; j < 4; j++) {
            float x0 = f[2 * j], x1 = f[2 * j + 1];
            __nv_bfloat162 h = __floats2bfloat162_rn(x0, x1);
            __nv_bfloat162 l = __floats2bfloat162_rn(x0 - __low2float(h),
                                                     x1 - __high2float(h));
            *(__nv_bfloat162*)(pAh + 2 * j) = h;
            *(__nv_bfloat162*)(pAl + 2 * j) = l;
        }
        // ---- fill B (already split bf16, [n][k]) ----
        *pBh = gBh[ks / 8];
        *pBl = gBl[ks / 8];
        __syncthreads();

        uint32_t Af[4][4], Bf[2][4];
        // term 1: Ah x Bh
        #pragma unroll
        for (int fm = 0; fm < 4; fm++) ldsm_x4(Af[fm], a_h[fm]);
        ldsm_x4(Bf[0], b_h[0]);
        ldsm_x4(Bf[1], b_h[1]);
        #pragma unroll
        for (int fm = 0; fm < 4; fm++)
            #pragma unroll
            for (int fn = 0; fn < 4; fn++)
                mma_bf16(acc[fm * 4 + fn], Af[fm],
                         Bf[fn >> 1][(fn & 1) * 2], Bf[fn >> 1][(fn & 1) * 2 + 1]);
        // term 2: Al x Bh (B frags still loaded)
        #pragma unroll
        for (int fm = 0; fm < 4; fm++) ldsm_x4(Af[fm], a_l[fm]);
        #pragma unroll
        for (int fm = 0; fm < 4; fm++)
            #pragma unroll
            for (int fn = 0; fn < 4; fn++)
                mma_bf16(acc[fm * 4 + fn], Af[fm],
                         Bf[fn >> 1][(fn & 1) * 2], Bf[fn >> 1][(fn & 1) * 2 + 1]);
        // term 3: Ah x Bl
        ldsm_x4(Bf[0], b_l[0]);
        ldsm_x4(Bf[1], b_l[1]);
        #pragma unroll
        for (int fm = 0; fm < 4; fm++) ldsm_x4(Af[fm], a_h[fm]);
        #pragma unroll
        for (int fm = 0; fm < 4; fm++)
            #pragma unroll
            for (int fn = 0; fn < 4; fn++)
                mma_bf16(acc[fm * 4 + fn], Af[fm],
                         Bf[fn >> 1][(fn & 1) * 2], Bf[fn >> 1][(fn & 1) * 2 + 1]);
    }

    // ---- epilogue: add bias, store ----
    #pragma unroll
    for (int fm = 0; fm < 4; fm++) {
        int r0 = m0 + wm0 + fm * 16 + (lane >> 2);
        #pragma unroll
        for (int fn = 0; fn < 4; fn++) {
            int col = n0 + wn0 + fn * 8 + (lane & 3) * 2;
            float2 bv = *(const float2*)(bias + col);
            float* a4 = acc[fm * 4 + fn];
            if (r0 < M) {
                float2 o = make_float2(a4[0] + bv.x, a4[1] + bv.y);
                *(float2*)(C + (long long)r0 * 256 + col) = o;
            }
            int r1 = r0 + 8;
            if (r1 < M) {
                float2 o = make_float2(a4[2] + bv.x, a4[3] + bv.y);
                *(float2*)(C + (long long)r1 * 256 + col) = o;
            }
        }
    }
}

// ------- fused conv1 CSR + softmax + skip + LN + ELU + conv2 projection ----
// One warp per dst node. Edge loop unrolled x2 with independent chains.
__global__ __launch_bounds__(256) void conv1_csr_kernel(
    const float* __restrict__ att1, const float* __restrict__ bias1,
    const float* __restrict__ gamma, const float* __restrict__ beta,
    const float* __restrict__ W2l, const float* __restrict__ b2l,
    const float* __restrict__ W2r, const float* __restrict__ b2r,
    const float* __restrict__ att2, int N)
{
    const int n = blockIdx.x * 8 + (threadIdx.x >> 5);
    const int lane = threadIdx.x & 31;
    if (n >= N) return;

    float attv[8];
    {
        float4 a0 = *(const float4*)(att1 + lane * 8);
        float4 a1 = *(const float4*)(att1 + lane * 8 + 4);
        attv[0]=a0.x; attv[1]=a0.y; attv[2]=a0.z; attv[3]=a0.w;
        attv[4]=a1.x; attv[5]=a1.y; attv[6]=a1.z; attv[7]=a1.w;
    }
    float xr[8];
    {
        const float* p = g_XR1 + (long long)n * HCc + lane * 8;
        float4 r0 = *(const float4*)p;
        float4 r1 = *(const float4*)(p + 4);
        xr[0]=r0.x; xr[1]=r0.y; xr[2]=r0.z; xr[3]=r0.w;
        xr[4]=r1.x; xr[5]=r1.y; xr[6]=r1.z; xr[7]=r1.w;
    }

    float acc[8], den;
    // self-loop
    {
        const float* p = g_XL1 + (long long)n * HCc + lane * 8;
        float4 l0 = *(const float4*)p;
        float4 l1 = *(const float4*)(p + 4);
        float xl[8] = {l0.x,l0.y,l0.z,l0.w,l1.x,l1.y,l1.z,l1.w};
        float s = 0.f;
        #pragma unroll
        for (int j = 0; j < 8; j++) {
            float e = xl[j] + xr[j];
            e = e > 0.f ? e : NEG * e;
            s = fmaf(e, attv[j], s);
        }
        s += __shfl_xor_sync(0xffffffffu, s, 1);
        s += __shfl_xor_sync(0xffffffffu, s, 2);
        s += __shfl_xor_sync(0xffffffffu, s, 4);
        float ex = expf(s);
        den = ex;
        #pragma unroll
        for (int j = 0; j < 8; j++) acc[j] = ex * xl[j];
    }

    const int row0 = g_rowptr[n];
    const int row1 = g_rowptr[n + 1];
    int i = row0;
    for (; i + 1 < row1; i += 2) {
        int srcA = g_esrc[i];
        int srcB = g_esrc[i + 1];
        const float* pA = g_XL1 + (long long)srcA * HCc + lane * 8;
        const float* pB = g_XL1 + (long long)srcB * HCc + lane * 8;
        float4 a0 = *(const float4*)pA;
        float4 a1 = *(const float4*)(pA + 4);
        float4 b0 = *(const float4*)pB;
        float4 b1 = *(const float4*)(pB + 4);
        float xlA[8] = {a0.x,a0.y,a0.z,a0.w,a1.x,a1.y,a1.z,a1.w};
        float xlB[8] = {b0.x,b0.y,b0.z,b0.w,b1.x,b1.y,b1.z,b1.w};
        float sA = 0.f, sB = 0.f;
        #pragma unroll
        for (int j = 0; j < 8; j++) {
            float eA = xlA[j] + xr[j];
            float eB = xlB[j] + xr[j];
            eA = eA > 0.f ? eA : NEG * eA;
            eB = eB > 0.f ? eB : NEG * eB;
            sA = fmaf(eA, attv[j], sA);
            sB = fmaf(eB, attv[j], sB);
        }
        #pragma unroll
        for (int o = 1; o <= 4; o <<= 1) {
            sA += __shfl_xor_sync(0xffffffffu, sA, o);
            sB += __shfl_xor_sync(0xffffffffu, sB, o);
        }
        float exA = expf(sA);
        float exB = expf(sB);
        den += exA + exB;
        #pragma unroll
        for (int j = 0; j < 8; j++) {
            acc[j] = fmaf(exA, xlA[j], acc[j]);
            acc[j] = fmaf(exB, xlB[j], acc[j]);
        }
    }
    if (i < row1) {
        int src = g_esrc[i];
        const float* p = g_XL1 + (long long)src * HCc + lane * 8;
        float4 l0 = *(const float4*)p;
        float4 l1 = *(const float4*)(p + 4);
        float xl[8] = {l0.x,l0.y,l0.z,l0.w,l1.x,l1.y,l1.z,l1.w};
        float s = 0.f;
        #pragma unroll
        for (int j = 0; j < 8; j++) {
            float e = xl[j] + xr[j];
            e = e > 0.f ? e : NEG * e;
            s = fmaf(e, attv[j], s);
        }
        s += __shfl_xor_sync(0xffffffffu, s, 1);
        s += __shfl_xor_sync(0xffffffffu, s, 2);
        s += __shfl_xor_sync(0xffffffffu, s, 4);
        float ex = expf(s);
        den += ex;
        #pragma unroll
        for (int j = 0; j < 8; j++) acc[j] = fmaf(ex, xl[j], acc[j]);
    }

    const float dinv = 1.0f / den;
    float v[8];
    {
        const float* sp = g_SKIP + (long long)n * HCc + lane * 8;
        float4 s0 = *(const float4*)sp;
        float4 s1 = *(const float4*)(sp + 4);
        float4 b0 = *(const float4*)(bias1 + lane * 8);
        float4 b1 = *(const float4*)(bias1 + lane * 8 + 4);
        float sk[8] = {s0.x,s0.y,s0.z,s0.w,s1.x,s1.y,s1.z,s1.w};
        float bb[8] = {b0.x,b0.y,b0.z,b0.w,b1.x,b1.y,b1.z,b1.w};
        #pragma unroll
        for (int j = 0; j < 8; j++) v[j] = acc[j] * dinv + bb[j] + sk[j];
    }

    float t = 0.f;
    #pragma unroll
    for (int j = 0; j < 8; j++) t += v[j];
    #pragma unroll
    for (int o = 16; o > 0; o >>= 1) t += __shfl_xor_sync(0xffffffffu, t, o);
    const float mu = t * (1.0f / 256.0f);
    float t2 = 0.f;
    #pragma unroll
    for (int j = 0; j < 8; j++) { float d = v[j] - mu; t2 = fmaf(d, d, t2); }
    #pragma unroll
    for (int o = 16; o > 0; o >>= 1) t2 += __shfl_xor_sync(0xffffffffu, t2, o);
    const float rstd = rsqrtf(t2 * (1.0f / 256.0f) + 1e-5f);

    float h[8];
    {
        float4 g0 = *(const float4*)(gamma + lane * 8);
        float4 g1 = *(const float4*)(gamma + lane * 8 + 4);
        float4 e0 = *(const float4*)(beta + lane * 8);
        float4 e1 = *(const float4*)(beta + lane * 8 + 4);
        float gg[8] = {g0.x,g0.y,g0.z,g0.w,g1.x,g1.y,g1.z,g1.w};
        float be[8] = {e0.x,e0.y,e0.z,e0.w,e1.x,e1.y,e1.z,e1.w};
        #pragma unroll
        for (int j = 0; j < 8; j++) {
            float hh = (v[j] - mu) * rstd * gg[j] + be[j];
            h[j] = hh > 0.f ? hh : expm1f(hh);
        }
    }

    float p0 = 0.f, p1 = 0.f, p2 = 0.f, p3 = 0.f;
    {
        const float* wl = W2l + lane * 16;
        const float* wr = W2r + lane * 16;
        float4 wl0 = *(const float4*)wl;
        float4 wl1 = *(const float4*)(wl + 4);
        float4 wl2 = *(const float4*)(wl + 8);
        float4 wl3 = *(const float4*)(wl + 12);
        float4 wr0 = *(const float4*)wr;
        float4 wr1 = *(const float4*)(wr + 4);
        float4 wr2 = *(const float4*)(wr + 8);
        float4 wr3 = *(const float4*)(wr + 12);
        float wlv[16] = {wl0.x,wl0.y,wl0.z,wl0.w, wl1.x,wl1.y,wl1.z,wl1.w,
                         wl2.x,wl2.y,wl2.z,wl2.w, wl3.x,wl3.y,wl3.z,wl3.w};
        float wrv[16] = {wr0.x,wr0.y,wr0.z,wr0.w, wr1.x,wr1.y,wr1.z,wr1.w,
                         wr2.x,wr2.y,wr2.z,wr2.w, wr3.x,wr3.y,wr3.z,wr3.w};
        #pragma unroll
        for (int j = 0; j < 8; j++) {
            p0 = fmaf(h[j], wlv[2 * j + 0], p0);
            p1 = fmaf(h[j], wlv[2 * j + 1], p1);
            p2 = fmaf(h[j], wrv[2 * j + 0], p2);
            p3 = fmaf(h[j], wrv[2 * j + 1], p3);
        }
    }
    #pragma unroll
    for (int o = 16; o > 0; o >>= 1) {
        p0 += __shfl_xor_sync(0xffffffffu, p0, o);
        p1 += __shfl_xor_sync(0xffffffffu, p1, o);
        p2 += __shfl_xor_sync(0xffffffffu, p2, o);
        p3 += __shfl_xor_sync(0xffffffffu, p3, o);
    }
    if (lane == 0) {
        float2 xl2, xr2;
        xl2.x = p0 + b2l[0]; xl2.y = p1 + b2l[1];
        xr2.x = p2 + b2r[0]; xr2.y = p3 + b2r[1];
        *(float2*)&g_XL2[n * 2] = xl2;
        *(float2*)&g_XR2[n * 2] = xr2;
    }
}

// ------------- conv2 CSR + final output (one thread per node) -------------
__global__ void conv2_csr_kernel(const float* __restrict__ att2,
                                 const float* __restrict__ bias2,
                                 float* __restrict__ out, int N) {
    int n = blockIdx.x * blockDim.x + threadIdx.x;
    if (n >= N) return;
    const float a0 = att2[0], a1 = att2[1];
    float2 xls = *(const float2*)&g_XL2[n * 2];
    float2 xr  = *(const float2*)&g_XR2[n * 2];
    float e0 = xls.x + xr.x; e0 = e0 > 0.f ? e0 : NEG * e0;
    float e1 = xls.y + xr.y; e1 = e1 > 0.f ? e1 : NEG * e1;
    float ex = expf(fmaf(e0, a0, e1 * a1));
    float den = ex, s0 = ex * xls.x, s1 = ex * xls.y;
    const int row0 = g_rowptr[n], row1 = g_rowptr[n + 1];
    for (int i = row0; i < row1; i++) {
        int src = g_esrc[i];
        float2 xl = *(const float2*)&g_XL2[src * 2];
        float f0 = xl.x + xr.x; f0 = f0 > 0.f ? f0 : NEG * f0;
        float f1 = xl.y + xr.y; f1 = f1 > 0.f ? f1 : NEG * f1;
        float exi = expf(fmaf(f0, a0, f1 * a1));
        den += exi;
        s0 = fmaf(exi, xl.x, s0);
        s1 = fmaf(exi, xl.y, s1);
    }
    float dinv = 1.0f / den;
    float2 o;
    o.x = s0 * dinv + bias2[0];
    o.y = s1 * dinv + bias2[1];
    *(float2*)(out + n * 2) = o;
}

// ---------------------------------------------------------------------------
extern "C" void kernel_launch(void* const* d_in, const int* in_sizes, int n_in,
                              void* d_out, int out_size) {
    const float* x     = (const float*)d_in[0];
    const void*  ei    = d_in[1];
    const float* W1l   = (const float*)d_in[2];
    const float* b1l   = (const float*)d_in[3];
    const float* W1r   = (const float*)d_in[4];
    const float* b1r   = (const float*)d_in[5];
    const float* att1  = (const float*)d_in[6];
    const float* bias1 = (const float*)d_in[7];
    const float* W2l   = (const float*)d_in[8];
    const float* b2l   = (const float*)d_in[9];
    const float* W2r   = (const float*)d_in[10];
    const float* b2r   = (const float*)d_in[11];
    const float* att2  = (const float*)d_in[12];
    const float* bias2 = (const float*)d_in[13];
    const float* Wskip = (const float*)d_in[14];
    const float* bskip = (const float*)d_in[15];
    const float* gamma = (const float*)d_in[16];
    const float* beta  = (const float*)d_in[17];
    float* out = (float*)d_out;

    const int       N = in_sizes[0] / DIN;            // 50000
    const long long E = (long long)in_sizes[1] / 2;   // 800000

    float *dXL1, *dXR1, *dSKIP;
    cudaGetSymbolAddress((void**)&dXL1, g_XL1);
    cudaGetSymbolAddress((void**)&dXR1, g_XR1);
    cudaGetSymbolAddress((void**)&dSKIP, g_SKIP);

    detect_idx_kernel<<<1, 1>>>((const unsigned int*)ei);

    // B prep (transpose + bf16 split)
    {
        dim3 g(256, 3);
        prep_b_kernel<<<g, 256>>>(W1l, W1r, Wskip);
    }

    // CSR build
    const int SB = (N + 1023) / 1024;
    zero_deg_kernel<<<(N + 255) / 256, 256>>>(N);
    hist_kernel<<<(int)((E + 255) / 256), 256>>>(ei, E);
    scanA_kernel<<<SB, 1024>>>(N);
    scanB_kernel<<<1, 32>>>(SB);
    scanC_kernel<<<SB, 1024>>>(N);
    scatter_kernel<<<(int)((E + 255) / 256), 256>>>(ei, E);

    // mma.sync bf16-split triple GEMM
    {
        dim3 g(6, (N + 127) / 128);
        gemm_mma_kernel<<<g, 256>>>(x, b1l, b1r, bskip, dXL1, dXR1, dSKIP, N);
    }

    // fused conv1 + epilogue (warp per node, 2-edge unroll, no atomics)
    conv1_csr_kernel<<<(N + 7) / 8, 256>>>(att1, bias1, gamma, beta,
                                           W2l, b2l, W2r, b2r, att2, N);

    // conv2 + final output
    conv2_csr_kernel<<<(N + 255) / 256, 256>>>(att2, bias2, out, N);
}

// round 9
// speedup vs baseline: 1.7633x; 1.2770x over previous
#include <cuda_runtime.h>
#include <cuda_bf16.h>
#include <math.h>
#include <stdint.h>

// Problem constants
#define DIN   256
#define HCc   256
#define NEG   0.2f
#define MAXN  50000
#define MAXE  1000000

// ---------------- scratch (static device globals) --------------------------
__device__ float g_XL1[(long long)MAXN * HCc];
__device__ float g_XR1[(long long)MAXN * HCc];
__device__ float g_SKIP[(long long)MAXN * HCc];
__device__ float g_XL2[MAXN * 2];
__device__ float g_XR2[MAXN * 2];
__device__ int   g_deg[MAXN];
__device__ int   g_rowptr[MAXN + 1];
__device__ int   g_cur[MAXN];
__device__ int   g_esrc[MAXE];
__device__ int   g_bsum[64];
__device__ int   g_boff[64];
__device__ int   g_is64;
// split-bf16 transposed weights: [sel][N=256][K=256]
__device__ __nv_bfloat16 g_BT_hi[3 * 256 * 256];
__device__ __nv_bfloat16 g_BT_lo[3 * 256 * 256];

// ---------------- small helpers ---------------------------------------------
__device__ __forceinline__ uint32_t smem_u32(const void* p) {
    uint32_t a;
    asm("{ .reg .u64 t; cvta.to.shared.u64 t, %1; cvt.u32.u64 %0, t; }"
        : "=r"(a) : "l"(p));
    return a;
}
__device__ __forceinline__ void ldsm_x4(uint32_t* r, uint32_t addr) {
    asm volatile("ldmatrix.sync.aligned.m8n8.x4.shared.b16 {%0,%1,%2,%3}, [%4];"
        : "=r"(r[0]), "=r"(r[1]), "=r"(r[2]), "=r"(r[3]) : "r"(addr));
}
__device__ __forceinline__ void mma_bf16(float* c, const uint32_t* a,
                                         uint32_t b0, uint32_t b1) {
    asm volatile(
        "mma.sync.aligned.m16n8k16.row.col.f32.bf16.bf16.f32 "
        "{%0,%1,%2,%3}, {%4,%5,%6,%7}, {%8,%9}, {%0,%1,%2,%3};"
        : "+f"(c[0]), "+f"(c[1]), "+f"(c[2]), "+f"(c[3])
        : "r"(a[0]), "r"(a[1]), "r"(a[2]), "r"(a[3]), "r"(b0), "r"(b1));
}
__device__ __forceinline__ void cp_async16(uint32_t dst, const void* src) {
    asm volatile("cp.async.ca.shared.global [%0], [%1], 16;"
                 :: "r"(dst), "l"(src) : "memory");
}
#define CP_COMMIT() asm volatile("cp.async.commit_group;" ::: "memory")
#define CP_WAIT0()  asm volatile("cp.async.wait_group 0;" ::: "memory")

// ---------------- dtype detection for edge_index (int32 vs int64) ---------
__global__ void detect_idx_kernel(const unsigned int* __restrict__ w) {
    int ok = 1;
    #pragma unroll
    for (int i = 0; i < 32; i++) {
        if (w[2 * i + 1] != 0u) { ok = 0; break; }
    }
    g_is64 = ok;
}
__device__ __forceinline__ int ld_idx(const void* ei, long long pos, int is64) {
    if (is64) return (int)(((const long long*)ei)[pos]);
    return ((const int*)ei)[pos];
}

// ---------------- CSR build -------------------------------------------------
__global__ void zero_deg_kernel(int N) {
    int i = blockIdx.x * blockDim.x + threadIdx.x;
    if (i < N) g_deg[i] = 0;
}
__global__ void hist_kernel(const void* __restrict__ ei, long long E) {
    long long e = (long long)blockIdx.x * blockDim.x + threadIdx.x;
    if (e >= E) return;
    int dst = ld_idx(ei, E + e, g_is64);
    atomicAdd(&g_deg[dst], 1);
}
__global__ __launch_bounds__(1024) void scanA_kernel(int N) {
    __shared__ int wsum[32];
    const int lane = threadIdx.x & 31, warp = threadIdx.x >> 5;
    int i = blockIdx.x * 1024 + threadIdx.x;
    int v = (i < N) ? g_deg[i] : 0;
    int x = v;
    #pragma unroll
    for (int o = 1; o < 32; o <<= 1) {
        int y = __shfl_up_sync(0xffffffffu, x, o);
        if (lane >= o) x += y;
    }
    if (lane == 31) wsum[warp] = x;
    __syncthreads();
    if (warp == 0) {
        int w = wsum[lane];
        #pragma unroll
        for (int o = 1; o < 32; o <<= 1) {
            int y = __shfl_up_sync(0xffffffffu, w, o);
            if (lane >= o) w += y;
        }
        wsum[lane] = w;
    }
    __syncthreads();
    int incl = x + (warp > 0 ? wsum[warp - 1] : 0);
    if (i < N) g_rowptr[i + 1] = incl;
    if (threadIdx.x == 1023) g_bsum[blockIdx.x] = incl;
}
__global__ void scanB_kernel(int B) {
    if (threadIdx.x == 0) {
        int acc = 0;
        for (int b = 0; b < B; b++) { int v = g_bsum[b]; g_boff[b] = acc; acc += v; }
    }
}
__global__ __launch_bounds__(1024) void scanC_kernel(int N) {
    int i = blockIdx.x * 1024 + threadIdx.x;
    if (i == 0) g_rowptr[0] = 0;
    if (i < N) {
        int r = g_rowptr[i + 1] + g_boff[blockIdx.x];
        g_rowptr[i + 1] = r;
        g_cur[i] = r - g_deg[i];
    }
}
__global__ void scatter_kernel(const void* __restrict__ ei, long long E) {
    long long e = (long long)blockIdx.x * blockDim.x + threadIdx.x;
    if (e >= E) return;
    int is64 = g_is64;
    int src = ld_idx(ei, e, is64);
    int dst = ld_idx(ei, E + e, is64);
    int pos = atomicAdd(&g_cur[dst], 1);
    g_esrc[pos] = src;
}

// ---------------- B prep: transpose + bf16 split ----------------------------
__global__ void prep_b_kernel(const float* __restrict__ W0,
                              const float* __restrict__ W1,
                              const float* __restrict__ W2) {
    int s = blockIdx.y, k = blockIdx.x, n = threadIdx.x;
    const float* W = (s == 0) ? W0 : (s == 1) ? W1 : W2;
    float v = W[k * 256 + n];
    __nv_bfloat16 hi = __float2bfloat16(v);
    float lo = v - __bfloat162float(hi);
    int idx = (s * 256 + n) * 256 + k;
    g_BT_hi[idx] = hi;
    g_BT_lo[idx] = __float2bfloat16(lo);
}

// ---------------- mma.sync bf16-split triple GEMM ---------------------------
// CTA 128m x 128n x K=256 (16 k-stages). 8 warps, each 64m x 32n.
// Double-buffered smem: B via cp.async (bf16 direct), A prefetched in regs.
#define PADK 24
#define ABUF (128 * PADK)          // bf16 elems per buffer
#define BUFB (ABUF * 2)            // byte offset between buffers

__global__ __launch_bounds__(256, 2) void gemm_mma_kernel(
    const float* __restrict__ A,
    const float* __restrict__ bias0, const float* __restrict__ bias1,
    const float* __restrict__ bias2,
    float* __restrict__ C0, float* __restrict__ C1, float* __restrict__ C2,
    int M)
{
    __shared__ __nv_bfloat16 sAh[2][ABUF];
    __shared__ __nv_bfloat16 sAl[2][ABUF];
    __shared__ __nv_bfloat16 sBh[2][ABUF];
    __shared__ __nv_bfloat16 sBl[2][ABUF];

    const int sel = blockIdx.x >> 1;
    const int n0  = (blockIdx.x & 1) * 128;
    const int m0  = blockIdx.y * 128;
    const float* bias = (sel == 0) ? bias0 : (sel == 1) ? bias1 : bias2;
    float*       C    = (sel == 0) ? C0 : (sel == 1) ? C1 : C2;
    const __nv_bfloat16* BTh = g_BT_hi + sel * 65536 + (long long)n0 * 256;
    const __nv_bfloat16* BTl = g_BT_lo + sel * 65536 + (long long)n0 * 256;

    const int tid  = threadIdx.x;
    const int lane = tid & 31;
    const int wid  = tid >> 5;
    const int wm0  = (wid >> 2) * 64;
    const int wn0  = (wid & 3) * 32;

    // fill mapping: thread t -> row ar (0..127), k-half ak (0 or 8)
    const int ar = tid >> 1;
    const int ak = (tid & 1) * 8;
    const bool arow_ok = (m0 + ar) < M;
    const float* Ap = A + (long long)(m0 + ar) * 256 + ak;
    const __nv_bfloat16* gBh = BTh + (long long)ar * 256 + ak;
    const __nv_bfloat16* gBl = BTl + (long long)ar * 256 + ak;
    __nv_bfloat16* pAh0 = &sAh[0][ar * PADK + ak];
    __nv_bfloat16* pAl0 = &sAl[0][ar * PADK + ak];
    const uint32_t dBh0 = smem_u32(&sBh[0][ar * PADK + ak]);
    const uint32_t dBl0 = smem_u32(&sBl[0][ar * PADK + ak]);

    // ldmatrix lane addresses for buffer 0 (add BUFB for buffer 1)
    uint32_t a_h[4], a_l[4], b_h[2], b_l[2];
    {
        int arow = lane & 15;
        int acol = (lane >> 4) * 8;
        #pragma unroll
        for (int fm = 0; fm < 4; fm++) {
            int idx = (wm0 + fm * 16 + arow) * PADK + acol;
            a_h[fm] = smem_u32(&sAh[0][idx]);
            a_l[fm] = smem_u32(&sAl[0][idx]);
        }
        int brow = (lane & 7) + (lane >> 4) * 8;
        int bcol = ((lane >> 3) & 1) * 8;
        #pragma unroll
        for (int nb = 0; nb < 2; nb++) {
            int idx = (wn0 + nb * 16 + brow) * PADK + bcol;
            b_h[nb] = smem_u32(&sBh[0][idx]);
            b_l[nb] = smem_u32(&sBl[0][idx]);
        }
    }

    float acc[16][4];
    #pragma unroll
    for (int i = 0; i < 16; i++)
        #pragma unroll
        for (int j = 0; j < 4; j++) acc[i][j] = 0.f;

    // ---- prologue: stage 0 into buffer 0 ----
    cp_async16(dBh0, gBh);
    cp_async16(dBl0, gBl);
    CP_COMMIT();
    float4 v0 = make_float4(0.f, 0.f, 0.f, 0.f);
    float4 v1 = make_float4(0.f, 0.f, 0.f, 0.f);
    if (arow_ok) { v0 = *(const float4*)Ap; v1 = *(const float4*)(Ap + 4); }
    {
        float f[8] = {v0.x, v0.y, v0.z, v0.w, v1.x, v1.y, v1.z, v1.w};
        #pragma unroll
        for (int j = 0; j < 4; j++) {
            __nv_bfloat162 h = __floats2bfloat162_rn(f[2*j], f[2*j+1]);
            __nv_bfloat162 l = __floats2bfloat162_rn(f[2*j]   - __low2float(h),
                                                     f[2*j+1] - __high2float(h));
            *(__nv_bfloat162*)(pAh0 + 2 * j) = h;
            *(__nv_bfloat162*)(pAl0 + 2 * j) = l;
        }
    }
    CP_WAIT0();
    __syncthreads();

    int buf = 0;
    for (int ks = 0; ks < 256; ks += 16) {
        const int nb = buf ^ 1;
        const bool has_next = (ks + 16) < 256;
        // ---- issue next stage's loads (B: cp.async, A: regs) ----
        if (has_next) {
            cp_async16(dBh0 + nb * BUFB, gBh + ks + 16);
            cp_async16(dBl0 + nb * BUFB, gBl + ks + 16);
            CP_COMMIT();
            v0 = make_float4(0.f, 0.f, 0.f, 0.f);
            v1 = make_float4(0.f, 0.f, 0.f, 0.f);
            if (arow_ok) {
                v0 = *(const float4*)(Ap + ks + 16);
                v1 = *(const float4*)(Ap + ks + 20);
            }
        }
        // ---- compute current buffer ----
        const uint32_t bofs = buf * BUFB;
        uint32_t Af[4][4], Bf[2][4];
        #pragma unroll
        for (int fm = 0; fm < 4; fm++) ldsm_x4(Af[fm], a_h[fm] + bofs);
        ldsm_x4(Bf[0], b_h[0] + bofs);
        ldsm_x4(Bf[1], b_h[1] + bofs);
        #pragma unroll
        for (int fm = 0; fm < 4; fm++)
            #pragma unroll
            for (int fn = 0; fn < 4; fn++)
                mma_bf16(acc[fm * 4 + fn], Af[fm],
                         Bf[fn >> 1][(fn & 1) * 2], Bf[fn >> 1][(fn & 1) * 2 + 1]);
        #pragma unroll
        for (int fm = 0; fm < 4; fm++) ldsm_x4(Af[fm], a_l[fm] + bofs);
        #pragma unroll
        for (int fm = 0; fm < 4; fm++)
            #pragma unroll
            for (int fn = 0; fn < 4; fn++)
                mma_bf16(acc[fm * 4 + fn], Af[fm],
                         Bf[fn >> 1][(fn & 1) * 2], Bf[fn >> 1][(fn & 1) * 2 + 1]);
        ldsm_x4(Bf[0], b_l[0] + bofs);
        ldsm_x4(Bf[1], b_l[1] + bofs);
        #pragma unroll
        for (int fm = 0; fm < 4; fm++) ldsm_x4(Af[fm], a_h[fm] + bofs);
        #pragma unroll
        for (int fm = 0; fm < 4; fm++)
            #pragma unroll
            for (int fn = 0; fn < 4; fn++)
                mma_bf16(acc[fm * 4 + fn], Af[fm],
                         Bf[fn >> 1][(fn & 1) * 2], Bf[fn >> 1][(fn & 1) * 2 + 1]);
        // ---- store prefetched A into next buffer; drain cp.async ----
        if (has_next) {
            float f[8] = {v0.x, v0.y, v0.z, v0.w, v1.x, v1.y, v1.z, v1.w};
            __nv_bfloat16* pAh = pAh0 + nb * ABUF;
            __nv_bfloat16* pAl = pAl0 + nb * ABUF;
            #pragma unroll
            for (int j = 0; j < 4; j++) {
                __nv_bfloat162 h = __floats2bfloat162_rn(f[2*j], f[2*j+1]);
                __nv_bfloat162 l = __floats2bfloat162_rn(f[2*j]   - __low2float(h),
                                                         f[2*j+1] - __high2float(h));
                *(__nv_bfloat162*)(pAh + 2 * j) = h;
                *(__nv_bfloat162*)(pAl + 2 * j) = l;
            }
            CP_WAIT0();
        }
        __syncthreads();
        buf = nb;
    }

    // ---- epilogue: add bias, store ----
    #pragma unroll
    for (int fm = 0; fm < 4; fm++) {
        int r0 = m0 + wm0 + fm * 16 + (lane >> 2);
        #pragma unroll
        for (int fn = 0; fn < 4; fn++) {
            int col = n0 + wn0 + fn * 8 + (lane & 3) * 2;
            float2 bv = *(const float2*)(bias + col);
            float* a4 = acc[fm * 4 + fn];
            if (r0 < M) {
                float2 o = make_float2(a4[0] + bv.x, a4[1] + bv.y);
                *(float2*)(C + (long long)r0 * 256 + col) = o;
            }
            int r1 = r0 + 8;
            if (r1 < M) {
                float2 o = make_float2(a4[2] + bv.x, a4[3] + bv.y);
                *(float2*)(C + (long long)r1 * 256 + col) = o;
            }
        }
    }
}

// ------- fused conv1 CSR + softmax + skip + LN + ELU + conv2 projection ----
__global__ __launch_bounds__(256) void conv1_csr_kernel(
    const float* __restrict__ att1, const float* __restrict__ bias1,
    const float* __restrict__ gamma, const float* __restrict__ beta,
    const float* __restrict__ W2l, const float* __restrict__ b2l,
    const float* __restrict__ W2r, const float* __restrict__ b2r,
    const float* __restrict__ att2, int N)
{
    const int n = blockIdx.x * 8 + (threadIdx.x >> 5);
    const int lane = threadIdx.x & 31;
    if (n >= N) return;

    float attv[8];
    {
        float4 a0 = *(const float4*)(att1 + lane * 8);
        float4 a1 = *(const float4*)(att1 + lane * 8 + 4);
        attv[0]=a0.x; attv[1]=a0.y; attv[2]=a0.z; attv[3]=a0.w;
        attv[4]=a1.x; attv[5]=a1.y; attv[6]=a1.z; attv[7]=a1.w;
    }
    float xr[8];
    {
        const float* p = g_XR1 + (long long)n * HCc + lane * 8;
        float4 r0 = *(const float4*)p;
        float4 r1 = *(const float4*)(p + 4);
        xr[0]=r0.x; xr[1]=r0.y; xr[2]=r0.z; xr[3]=r0.w;
        xr[4]=r1.x; xr[5]=r1.y; xr[6]=r1.z; xr[7]=r1.w;
    }

    float acc[8], den;
    // self-loop
    {
        const float* p = g_XL1 + (long long)n * HCc + lane * 8;
        float4 l0 = *(const float4*)p;
        float4 l1 = *(const float4*)(p + 4);
        float xl[8] = {l0.x,l0.y,l0.z,l0.w,l1.x,l1.y,l1.z,l1.w};
        float s = 0.f;
        #pragma unroll
        for (int j = 0; j < 8; j++) {
            float e = xl[j] + xr[j];
            e = e > 0.f ? e : NEG * e;
            s = fmaf(e, attv[j], s);
        }
        s += __shfl_xor_sync(0xffffffffu, s, 1);
        s += __shfl_xor_sync(0xffffffffu, s, 2);
        s += __shfl_xor_sync(0xffffffffu, s, 4);
        float ex = expf(s);
        den = ex;
        #pragma unroll
        for (int j = 0; j < 8; j++) acc[j] = ex * xl[j];
    }

    const int row0 = g_rowptr[n];
    const int row1 = g_rowptr[n + 1];
    int i = row0;
    for (; i + 1 < row1; i += 2) {
        int srcA = g_esrc[i];
        int srcB = g_esrc[i + 1];
        const float* pA = g_XL1 + (long long)srcA * HCc + lane * 8;
        const float* pB = g_XL1 + (long long)srcB * HCc + lane * 8;
        float4 a0 = *(const float4*)pA;
        float4 a1 = *(const float4*)(pA + 4);
        float4 b0 = *(const float4*)pB;
        float4 b1 = *(const float4*)(pB + 4);
        float xlA[8] = {a0.x,a0.y,a0.z,a0.w,a1.x,a1.y,a1.z,a1.w};
        float xlB[8] = {b0.x,b0.y,b0.z,b0.w,b1.x,b1.y,b1.z,b1.w};
        float sA = 0.f, sB = 0.f;
        #pragma unroll
        for (int j = 0; j < 8; j++) {
            float eA = xlA[j] + xr[j];
            float eB = xlB[j] + xr[j];
            eA = eA > 0.f ? eA : NEG * eA;
            eB = eB > 0.f ? eB : NEG * eB;
            sA = fmaf(eA, attv[j], sA);
            sB = fmaf(eB, attv[j], sB);
        }
        #pragma unroll
        for (int o = 1; o <= 4; o <<= 1) {
            sA += __shfl_xor_sync(0xffffffffu, sA, o);
            sB += __shfl_xor_sync(0xffffffffu, sB, o);
        }
        float exA = expf(sA);
        float exB = expf(sB);
        den += exA + exB;
        #pragma unroll
        for (int j = 0; j < 8; j++) {
            acc[j] = fmaf(exA, xlA[j], acc[j]);
            acc[j] = fmaf(exB, xlB[j], acc[j]);
        }
    }
    if (i < row1) {
        int src = g_esrc[i];
        const float* p = g_XL1 + (long long)src * HCc + lane * 8;
        float4 l0 = *(const float4*)p;
        float4 l1 = *(const float4*)(p + 4);
        float xl[8] = {l0.x,l0.y,l0.z,l0.w,l1.x,l1.y,l1.z,l1.w};
        float s = 0.f;
        #pragma unroll
        for (int j = 0; j < 8; j++) {
            float e = xl[j] + xr[j];
            e = e > 0.f ? e : NEG * e;
            s = fmaf(e, attv[j], s);
        }
        s += __shfl_xor_sync(0xffffffffu, s, 1);
        s += __shfl_xor_sync(0xffffffffu, s, 2);
        s += __shfl_xor_sync(0xffffffffu, s, 4);
        float ex = expf(s);
        den += ex;
        #pragma unroll
        for (int j = 0; j < 8; j++) acc[j] = fmaf(ex, xl[j], acc[j]);
    }

    const float dinv = 1.0f / den;
    float v[8];
    {
        const float* sp = g_SKIP + (long long)n * HCc + lane * 8;
        float4 s0 = *(const float4*)sp;
        float4 s1 = *(const float4*)(sp + 4);
        float4 b0 = *(const float4*)(bias1 + lane * 8);
        float4 b1 = *(const float4*)(bias1 + lane * 8 + 4);
        float sk[8] = {s0.x,s0.y,s0.z,s0.w,s1.x,s1.y,s1.z,s1.w};
        float bb[8] = {b0.x,b0.y,b0.z,b0.w,b1.x,b1.y,b1.z,b1.w};
        #pragma unroll
        for (int j = 0; j < 8; j++) v[j] = acc[j] * dinv + bb[j] + sk[j];
    }

    float t = 0.f;
    #pragma unroll
    for (int j = 0; j < 8; j++) t += v[j];
    #pragma unroll
    for (int o = 16; o > 0; o >>= 1) t += __shfl_xor_sync(0xffffffffu, t, o);
    const float mu = t * (1.0f / 256.0f);
    float t2 = 0.f;
    #pragma unroll
    for (int j = 0; j < 8; j++) { float d = v[j] - mu; t2 = fmaf(d, d, t2); }
    #pragma unroll
    for (int o = 16; o > 0; o >>= 1) t2 += __shfl_xor_sync(0xffffffffu, t2, o);
    const float rstd = rsqrtf(t2 * (1.0f / 256.0f) + 1e-5f);

    float h[8];
    {
        float4 g0 = *(const float4*)(gamma + lane * 8);
        float4 g1 = *(const float4*)(gamma + lane * 8 + 4);
        float4 e0 = *(const float4*)(beta + lane * 8);
        float4 e1 = *(const float4*)(beta + lane * 8 + 4);
        float gg[8] = {g0.x,g0.y,g0.z,g0.w,g1.x,g1.y,g1.z,g1.w};
        float be[8] = {e0.x,e0.y,e0.z,e0.w,e1.x,e1.y,e1.z,e1.w};
        #pragma unroll
        for (int j = 0; j < 8; j++) {
            float hh = (v[j] - mu) * rstd * gg[j] + be[j];
            h[j] = hh > 0.f ? hh : expm1f(hh);
        }
    }

    float p0 = 0.f, p1 = 0.f, p2 = 0.f, p3 = 0.f;
    {
        const float* wl = W2l + lane * 16;
        const float* wr = W2r + lane * 16;
        float4 wl0 = *(const float4*)wl;
        float4 wl1 = *(const float4*)(wl + 4);
        float4 wl2 = *(const float4*)(wl + 8);
        float4 wl3 = *(const float4*)(wl + 12);
        float4 wr0 = *(const float4*)wr;
        float4 wr1 = *(const float4*)(wr + 4);
        float4 wr2 = *(const float4*)(wr + 8);
        float4 wr3 = *(const float4*)(wr + 12);
        float wlv[16] = {wl0.x,wl0.y,wl0.z,wl0.w, wl1.x,wl1.y,wl1.z,wl1.w,
                         wl2.x,wl2.y,wl2.z,wl2.w, wl3.x,wl3.y,wl3.z,wl3.w};
        float wrv[16] = {wr0.x,wr0.y,wr0.z,wr0.w, wr1.x,wr1.y,wr1.z,wr1.w,
                         wr2.x,wr2.y,wr2.z,wr2.w, wr3.x,wr3.y,wr3.z,wr3.w};
        #pragma unroll
        for (int j = 0; j < 8; j++) {
            p0 = fmaf(h[j], wlv[2 * j + 0], p0);
            p1 = fmaf(h[j], wlv[2 * j + 1], p1);
            p2 = fmaf(h[j], wrv[2 * j + 0], p2);
            p3 = fmaf(h[j], wrv[2 * j + 1], p3);
        }
    }
    #pragma unroll
    for (int o = 16; o > 0; o >>= 1) {
        p0 += __shfl_xor_sync(0xffffffffu, p0, o);
        p1 += __shfl_xor_sync(0xffffffffu, p1, o);
        p2 += __shfl_xor_sync(0xffffffffu, p2, o);
        p3 += __shfl_xor_sync(0xffffffffu, p3, o);
    }
    if (lane == 0) {
        float2 xl2, xr2;
        xl2.x = p0 + b2l[0]; xl2.y = p1 + b2l[1];
        xr2.x = p2 + b2r[0]; xr2.y = p3 + b2r[1];
        *(float2*)&g_XL2[n * 2] = xl2;
        *(float2*)&g_XR2[n * 2] = xr2;
    }
}

// ------------- conv2 CSR + final output (one thread per node) -------------
__global__ void conv2_csr_kernel(const float* __restrict__ att2,
                                 const float* __restrict__ bias2,
                                 float* __restrict__ out, int N) {
    int n = blockIdx.x * blockDim.x + threadIdx.x;
    if (n >= N) return;
    const float a0 = att2[0], a1 = att2[1];
    float2 xls = *(const float2*)&g_XL2[n * 2];
    float2 xr  = *(const float2*)&g_XR2[n * 2];
    float e0 = xls.x + xr.x; e0 = e0 > 0.f ? e0 : NEG * e0;
    float e1 = xls.y + xr.y; e1 = e1 > 0.f ? e1 : NEG * e1;
    float ex = expf(fmaf(e0, a0, e1 * a1));
    float den = ex, s0 = ex * xls.x, s1 = ex * xls.y;
    const int row0 = g_rowptr[n], row1 = g_rowptr[n + 1];
    for (int i = row0; i < row1; i++) {
        int src = g_esrc[i];
        float2 xl = *(const float2*)&g_XL2[src * 2];
        float f0 = xl.x + xr.x; f0 = f0 > 0.f ? f0 : NEG * f0;
        float f1 = xl.y + xr.y; f1 = f1 > 0.f ? f1 : NEG * f1;
        float exi = expf(fmaf(f0, a0, f1 * a1));
        den += exi;
        s0 = fmaf(exi, xl.x, s0);
        s1 = fmaf(exi, xl.y, s1);
    }
    float dinv = 1.0f / den;
    float2 o;
    o.x = s0 * dinv + bias2[0];
    o.y = s1 * dinv + bias2[1];
    *(float2*)(out + n * 2) = o;
}

// ---------------------------------------------------------------------------
extern "C" void kernel_launch(void* const* d_in, const int* in_sizes, int n_in,
                              void* d_out, int out_size) {
    const float* x     = (const float*)d_in[0];
    const void*  ei    = d_in[1];
    const float* W1l   = (const float*)d_in[2];
    const float* b1l   = (const float*)d_in[3];
    const float* W1r   = (const float*)d_in[4];
    const float* b1r   = (const float*)d_in[5];
    const float* att1  = (const float*)d_in[6];
    const float* bias1 = (const float*)d_in[7];
    const float* W2l   = (const float*)d_in[8];
    const float* b2l   = (const float*)d_in[9];
    const float* W2r   = (const float*)d_in[10];
    const float* b2r   = (const float*)d_in[11];
    const float* att2  = (const float*)d_in[12];
    const float* bias2 = (const float*)d_in[13];
    const float* Wskip = (const float*)d_in[14];
    const float* bskip = (const float*)d_in[15];
    const float* gamma = (const float*)d_in[16];
    const float* beta  = (const float*)d_in[17];
    float* out = (float*)d_out;

    const int       N = in_sizes[0] / DIN;            // 50000
    const long long E = (long long)in_sizes[1] / 2;   // 800000

    float *dXL1, *dXR1, *dSKIP;
    cudaGetSymbolAddress((void**)&dXL1, g_XL1);
    cudaGetSymbolAddress((void**)&dXR1, g_XR1);
    cudaGetSymbolAddress((void**)&dSKIP, g_SKIP);

    // launch order places gemm at ncu capture slot (-s 5): indices
    // 0:detect 1:prep 2:zero 3:hist 4:scanA 5:gemm 6:scanB 7:scanC 8:scatter
    // 9:conv1 10:conv2  (all dependencies respected in-stream)
    detect_idx_kernel<<<1, 1>>>((const unsigned int*)ei);
    {
        dim3 g(256, 3);
        prep_b_kernel<<<g, 256>>>(W1l, W1r, Wskip);
    }
    const int SB = (N + 1023) / 1024;
    zero_deg_kernel<<<(N + 255) / 256, 256>>>(N);
    hist_kernel<<<(int)((E + 255) / 256), 256>>>(ei, E);
    scanA_kernel<<<SB, 1024>>>(N);
    {
        dim3 g(6, (N + 127) / 128);
        gemm_mma_kernel<<<g, 256>>>(x, b1l, b1r, bskip, dXL1, dXR1, dSKIP, N);
    }
    scanB_kernel<<<1, 32>>>(SB);
    scanC_kernel<<<SB, 1024>>>(N);
    scatter_kernel<<<(int)((E + 255) / 256), 256>>>(ei, E);

    conv1_csr_kernel<<<(N + 7) / 8, 256>>>(att1, bias1, gamma, beta,
                                           W2l, b2l, W2r, b2r, att2, N);
    conv2_csr_kernel<<<(N + 255) / 256, 256>>>(att2, bias2, out, N);
}